// round 6
// baseline (speedup 1.0000x reference)
#include <cuda_runtime.h>
#include <cuda_bf16.h>
#include <cstdint>
#include <cstddef>

#define NTOK 8192
#define HDIM 1024
#define NEXP 8
#define TOPK 2
#define IDIM 1024
#define SHI  2048
#define CAP  2560   // ceil(1.25 * 8192 * 2 / 8)

// ---------------- device scratch ----------------
__device__ int   g_topk_idx[NTOK * TOPK];
__device__ float g_topk_w[NTOK * TOPK];
__device__ int   g_etok[NEXP * CAP];
__device__ float g_ewt[NEXP * CAP];
__device__ int   g_counts[NEXP];

// int8 hi/lo operands + per-row scales
__device__ __align__(128) int8_t g_xh[NTOK * HDIM],  g_xl[NTOK * HDIM];
__device__ float g_sx[NTOK];
__device__ __align__(128) int8_t g_wgh[NEXP * IDIM * HDIM], g_wgl[NEXP * IDIM * HDIM];
__device__ float g_swg[NEXP * IDIM];
__device__ __align__(128) int8_t g_wuh[NEXP * IDIM * HDIM], g_wul[NEXP * IDIM * HDIM];
__device__ float g_swu[NEXP * IDIM];
__device__ __align__(128) int8_t g_wdh[NEXP * HDIM * IDIM], g_wdl[NEXP * HDIM * IDIM];
__device__ float g_swd[NEXP * HDIM];
__device__ __align__(128) int8_t g_sgh[SHI * HDIM], g_sgl[SHI * HDIM];
__device__ float g_ssg[SHI];
__device__ __align__(128) int8_t g_suh[SHI * HDIM], g_sul[SHI * HDIM];
__device__ float g_ssu[SHI];
__device__ __align__(128) int8_t g_sdh[HDIM * SHI], g_sdl[HDIM * SHI];
__device__ float g_ssd[HDIM];

// fp32 gate/up GEMM outputs
__device__ __align__(128) float g_gr[(size_t)NEXP * CAP * IDIM];
__device__ __align__(128) float g_ur[(size_t)NEXP * CAP * IDIM];
__device__ __align__(128) float g_gs[(size_t)NTOK * SHI];
__device__ __align__(128) float g_us[(size_t)NTOK * SHI];

// quantized activations
__device__ __align__(128) int8_t g_arh[(size_t)NEXP * CAP * IDIM], g_arl[(size_t)NEXP * CAP * IDIM];
__device__ float g_sar[NEXP * CAP];
__device__ __align__(128) int8_t g_ash[(size_t)NTOK * SHI], g_asl[(size_t)NTOK * SHI];
__device__ float g_sas[NTOK];

__device__ __forceinline__ float silu_f(float x) { return x / (1.f + __expf(-x)); }
__device__ __forceinline__ uint32_t sw64(uint32_t b) { return b ^ ((b >> 3) & 0x30); }

__device__ __forceinline__ void cp16(uint32_t dst, const void* src) {
    asm volatile("cp.async.cg.shared.global [%0], [%1], 16;" :: "r"(dst), "l"(src));
}
#define CP_COMMIT() asm volatile("cp.async.commit_group;")
#define CP_WAIT2()  asm volatile("cp.async.wait_group 2;")

__device__ __forceinline__ void ldsm4(uint32_t* r, uint32_t addr) {
    asm volatile("ldmatrix.sync.aligned.m8n8.x4.shared.b16 {%0,%1,%2,%3}, [%4];"
                 : "=r"(r[0]), "=r"(r[1]), "=r"(r[2]), "=r"(r[3]) : "r"(addr));
}

__device__ __forceinline__ void imma(int (&c)[4], const uint32_t (&a)[4],
                                     uint32_t b0, uint32_t b1)
{
    asm volatile(
        "mma.sync.aligned.m16n8k32.row.col.s32.s8.s8.s32 "
        "{%0,%1,%2,%3}, {%4,%5,%6,%7}, {%8,%9}, {%0,%1,%2,%3};\n"
        : "+r"(c[0]), "+r"(c[1]), "+r"(c[2]), "+r"(c[3])
        : "r"(a[0]), "r"(a[1]), "r"(a[2]), "r"(a[3]), "r"(b0), "r"(b1));
}

// ---------------- row quantization: x -> s*(h + l/127) ----------------
__device__ void quant_row(const float* __restrict__ src, int8_t* __restrict__ h,
                          int8_t* __restrict__ l, float* __restrict__ sc,
                          int row, int K)
{
    const float* p = src + (size_t)row * K;
    int lane = threadIdx.x & 31;
    float amax = 0.f;
    for (int k = lane * 4; k < K; k += 128) {
        float4 v = *(const float4*)(p + k);
        amax = fmaxf(amax, fmaxf(fmaxf(fabsf(v.x), fabsf(v.y)), fmaxf(fabsf(v.z), fabsf(v.w))));
    }
#pragma unroll
    for (int off = 16; off > 0; off >>= 1)
        amax = fmaxf(amax, __shfl_xor_sync(0xffffffffu, amax, off));
    float s = fmaxf(amax, 1e-20f) * (1.f / 127.f);
    float inv = 1.f / s;
    if (lane == 0) sc[row] = s;
    int8_t* hr = h + (size_t)row * K;
    int8_t* lr = l + (size_t)row * K;
    for (int k = lane * 4; k < K; k += 128) {
        float4 v = *(const float4*)(p + k);
        float f[4] = { v.x, v.y, v.z, v.w };
        char hb[4], lb[4];
#pragma unroll
        for (int j = 0; j < 4; j++) {
            float hv = rintf(f[j] * inv);
            float rv = f[j] - hv * s;
            float lv = rintf(rv * inv * 127.f);
            hb[j] = (char)(int)hv;
            lb[j] = (char)(int)lv;
        }
        *(char4*)(hr + k) = make_char4(hb[0], hb[1], hb[2], hb[3]);
        *(char4*)(lr + k) = make_char4(lb[0], lb[1], lb[2], lb[3]);
    }
}

// one launch: quantize x + all weights (warp per row)
__global__ void quant_all_kernel(
    const float* __restrict__ x,  const float* __restrict__ wg,
    const float* __restrict__ wu, const float* __restrict__ wd,
    const float* __restrict__ sg, const float* __restrict__ su,
    const float* __restrict__ sd)
{
    int row = blockIdx.x * 8 + (threadIdx.x >> 5);
    if (row < 8192)  { quant_row(x,  g_xh,  g_xl,  g_sx,  row, HDIM); return; }
    row -= 8192;
    if (row < 8192)  { quant_row(wg, g_wgh, g_wgl, g_swg, row, HDIM); return; }
    row -= 8192;
    if (row < 8192)  { quant_row(wu, g_wuh, g_wul, g_swu, row, HDIM); return; }
    row -= 8192;
    if (row < 8192)  { quant_row(wd, g_wdh, g_wdl, g_swd, row, IDIM); return; }
    row -= 8192;
    if (row < 2048)  { quant_row(sg, g_sgh, g_sgl, g_ssg, row, HDIM); return; }
    row -= 2048;
    if (row < 2048)  { quant_row(su, g_suh, g_sul, g_ssu, row, HDIM); return; }
    row -= 2048;
    if (row < 1024)  { quant_row(sd, g_sdh, g_sdl, g_ssd, row, SHI);  return; }
}

// ---------------- SwiGLU + activation quantization (warp per row) ----------------
__global__ void act_quant_kernel()
{
    int row = blockIdx.x * 8 + (threadIdx.x >> 5);
    int lane = threadIdx.x & 31;
    const float *gp, *up; int8_t *hp, *lp; float* scp; int K, srow;
    if (row < NEXP * CAP) {
        K = IDIM; srow = row;
        gp = g_gr + (size_t)row * K;  up = g_ur + (size_t)row * K;
        hp = g_arh + (size_t)row * K; lp = g_arl + (size_t)row * K; scp = g_sar;
    } else {
        row -= NEXP * CAP;
        if (row >= NTOK) return;
        K = SHI; srow = row;
        gp = g_gs + (size_t)row * K;  up = g_us + (size_t)row * K;
        hp = g_ash + (size_t)row * K; lp = g_asl + (size_t)row * K; scp = g_sas;
    }
    float4 av[16];
    int nIter = K / 128;
    float amax = 0.f;
    for (int it = 0; it < nIter; it++) {
        int k = it * 128 + lane * 4;
        float4 g = *(const float4*)(gp + k);
        float4 u = *(const float4*)(up + k);
        float4 a;
        a.x = silu_f(g.x) * u.x; a.y = silu_f(g.y) * u.y;
        a.z = silu_f(g.z) * u.z; a.w = silu_f(g.w) * u.w;
        av[it] = a;
        amax = fmaxf(amax, fmaxf(fmaxf(fabsf(a.x), fabsf(a.y)), fmaxf(fabsf(a.z), fabsf(a.w))));
    }
#pragma unroll
    for (int off = 16; off > 0; off >>= 1)
        amax = fmaxf(amax, __shfl_xor_sync(0xffffffffu, amax, off));
    float s = fmaxf(amax, 1e-20f) * (1.f / 127.f);
    float inv = 1.f / s;
    if (lane == 0) scp[srow] = s;
    for (int it = 0; it < nIter; it++) {
        int k = it * 128 + lane * 4;
        float f[4] = { av[it].x, av[it].y, av[it].z, av[it].w };
        char hb[4], lb[4];
#pragma unroll
        for (int j = 0; j < 4; j++) {
            float hv = rintf(f[j] * inv);
            float rv = f[j] - hv * s;
            float lv = rintf(rv * inv * 127.f);
            hb[j] = (char)(int)hv;
            lb[j] = (char)(int)lv;
        }
        *(char4*)(hp + k) = make_char4(hb[0], hb[1], hb[2], hb[3]);
        *(char4*)(lp + k) = make_char4(lb[0], lb[1], lb[2], lb[3]);
    }
}

// ---------------- router ----------------
__global__ void router_kernel(const float* __restrict__ x, const float* __restrict__ gw)
{
    int warp = threadIdx.x >> 5;
    int lane = threadIdx.x & 31;
    int tok  = blockIdx.x * 8 + warp;
    if (tok >= NTOK) return;
    const float* xr = x + (size_t)tok * HDIM;

    float acc[NEXP];
#pragma unroll
    for (int e = 0; e < NEXP; e++) acc[e] = 0.f;
    for (int h = lane; h < HDIM; h += 32) {
        float xv = xr[h];
#pragma unroll
        for (int e = 0; e < NEXP; e++) acc[e] += xv * gw[e * HDIM + h];
    }
#pragma unroll
    for (int e = 0; e < NEXP; e++) {
#pragma unroll
        for (int off = 16; off > 0; off >>= 1)
            acc[e] += __shfl_xor_sync(0xffffffffu, acc[e], off);
    }
    if (lane == 0) {
        float mx = acc[0];
#pragma unroll
        for (int e = 1; e < NEXP; e++) mx = fmaxf(mx, acc[e]);
        float p[NEXP]; float s = 0.f;
#pragma unroll
        for (int e = 0; e < NEXP; e++) { p[e] = expf(acc[e] - mx); s += p[e]; }
#pragma unroll
        for (int e = 0; e < NEXP; e++) p[e] /= s;
        int i0 = 0;
#pragma unroll
        for (int e = 1; e < NEXP; e++) if (p[e] > p[i0]) i0 = e;
        int i1 = -1;
#pragma unroll
        for (int e = 0; e < NEXP; e++) {
            if (e == i0) continue;
            if (i1 < 0 || p[e] > p[i1]) i1 = e;
        }
        float w0 = p[i0], w1 = p[i1];
        float inv = 1.f / (w0 + w1 + 1e-20f);
        g_topk_idx[tok * 2 + 0] = i0;
        g_topk_idx[tok * 2 + 1] = i1;
        g_topk_w[tok * 2 + 0] = w0 * inv;
        g_topk_w[tok * 2 + 1] = w1 * inv;
    }
}

// ---------------- capacity scan + compaction (reference order) ----------------
__global__ void scan_kernel()
{
    __shared__ int hist[256][NEXP];
    int t = threadIdx.x;
    const int per = (NTOK * TOPK) / 256;
    int local[NEXP];
#pragma unroll
    for (int e = 0; e < NEXP; e++) local[e] = 0;
    int base = t * per;
    for (int i = 0; i < per; i++) local[g_topk_idx[base + i]]++;
#pragma unroll
    for (int e = 0; e < NEXP; e++) hist[t][e] = local[e];
    __syncthreads();
    if (t < NEXP) {
        int run = 0;
        for (int i = 0; i < 256; i++) { int v = hist[i][t]; hist[i][t] = run; run += v; }
        g_counts[t] = run < CAP ? run : CAP;
    }
    __syncthreads();
    int off[NEXP];
#pragma unroll
    for (int e = 0; e < NEXP; e++) off[e] = hist[t][e];
    for (int i = 0; i < per; i++) {
        int slot = base + i;
        int e = g_topk_idx[slot];
        int pos = off[e]++;
        if (pos < CAP) {
            g_etok[e * CAP + pos] = slot >> 1;
            g_ewt[e * CAP + pos]  = g_topk_w[slot];
        }
    }
}

// ============================================================================
// int8 GEMM: C[m,n] = sa[m]*sb[n]*(A@B^T)  (2-level int8, 3 IMMA products)
// CTA 128x64, stage K=64 bytes, 3-stage cp.async, 8 warps, warp tile 32x32.
// Modes: plain fp32 tile out (gate/up), or scatter (+atomic) to d_out (down).
// ============================================================================
#define STG_B 24576   // AH 8K | AL 8K | BH 4K | BL 4K

__global__ __launch_bounds__(256, 1) void gemm_s8_kernel(
    const int8_t* __restrict__ Ah_, const int8_t* __restrict__ Al_, int lda, size_t a_estride,
    const int* __restrict__ arowidx,
    const int8_t* __restrict__ Bh_, const int8_t* __restrict__ Bl_, size_t b_estride,
    const float* __restrict__ sa_arr, int sa_estride,
    const float* __restrict__ sb_arr, int sb_estride,
    float* __restrict__ outf, size_t o_estride, int ldo,
    float* __restrict__ outscat, const int* __restrict__ scatidx,
    const float* __restrict__ wts, int accumulate,
    const int* __restrict__ counts, int Kdim)
{
    extern __shared__ __align__(128) char smdyn[];
    const int e = blockIdx.z;
    const int m0 = blockIdx.y * 128, n0 = blockIdx.x * 64;
    if (counts && m0 >= counts[e]) return;

    const int tid = threadIdx.x, lane = tid & 31, warp = tid >> 5;
    const int wm = warp & 3, wn = warp >> 2;
    uint32_t smb = (uint32_t)__cvta_generic_to_shared(smdyn);
    const int AH = 0, AL = 8192, BH = 16384, BL = 20480;

    // loader: thread -> A rows (ar0, ar0+64) + B row ar0, 16B chunk ac
    const int ar0 = tid >> 2, ac = tid & 3;
    int arow0 = m0 + ar0, arow1 = arow0 + 64;
    int t0 = arowidx ? arowidx[e * CAP + arow0] : arow0;
    int t1 = arowidx ? arowidx[e * CAP + arow1] : arow1;
    size_t ab0 = (size_t)e * a_estride + (size_t)t0 * lda + ac * 16;
    size_t ab1 = (size_t)e * a_estride + (size_t)t1 * lda + ac * 16;
    size_t bb  = (size_t)e * b_estride + (size_t)(n0 + ar0) * Kdim + ac * 16;
    uint32_t dsw0 = sw64(ar0 * 64 + ac * 16);
    uint32_t dsw1 = sw64((ar0 + 64) * 64 + ac * 16);

    auto fill = [&](int kt, int buf) {
        uint32_t s = smb + buf * STG_B;
        long kb = (long)kt * 64;
        cp16(s + AH + dsw0, Ah_ + ab0 + kb);
        cp16(s + AH + dsw1, Ah_ + ab1 + kb);
        cp16(s + AL + dsw0, Al_ + ab0 + kb);
        cp16(s + AL + dsw1, Al_ + ab1 + kb);
        cp16(s + BH + dsw0, Bh_ + bb + kb);
        cp16(s + BL + dsw0, Bl_ + bb + kb);
    };

    const int lr = lane & 15, lc = (lane >> 4) * 16;

    int hh[2][4][4], hl[2][4][4];
#pragma unroll
    for (int mt = 0; mt < 2; mt++)
#pragma unroll
        for (int nf = 0; nf < 4; nf++)
#pragma unroll
            for (int i = 0; i < 4; i++) { hh[mt][nf][i] = 0; hl[mt][nf][i] = 0; }

    auto comp = [&](int buf) {
        uint32_t s = smb + buf * STG_B;
#pragma unroll
        for (int kk = 0; kk < 2; kk++) {
            uint32_t ah[2][4], al[2][4];
#pragma unroll
            for (int mt = 0; mt < 2; mt++) {
                uint32_t o = sw64((wm * 32 + mt * 16 + lr) * 64 + kk * 32 + lc);
                ldsm4(ah[mt], s + AH + o);
                ldsm4(al[mt], s + AL + o);
            }
            uint32_t bh[2][4], bl[2][4];
#pragma unroll
            for (int nt = 0; nt < 2; nt++) {
                uint32_t o = sw64((wn * 32 + nt * 16 + lr) * 64 + kk * 32 + lc);
                ldsm4(bh[nt], s + BH + o);
                ldsm4(bl[nt], s + BL + o);
            }
#pragma unroll
            for (int mt = 0; mt < 2; mt++) {
#pragma unroll
                for (int nf = 0; nf < 4; nf++) {
                    int nt = nf >> 1, sb = nf & 1;
                    imma(hh[mt][nf], ah[mt], bh[nt][sb], bh[nt][sb + 2]);
                    imma(hl[mt][nf], ah[mt], bl[nt][sb], bl[nt][sb + 2]);
                    imma(hl[mt][nf], al[mt], bh[nt][sb], bh[nt][sb + 2]);
                }
            }
        }
    };

    const int KT = Kdim >> 6;
    fill(0, 0); CP_COMMIT();
    fill(1, 1); CP_COMMIT();
    for (int kt = 0; kt < KT; kt++) {
        int nk = kt + 2;
        if (nk < KT) fill(nk, nk % 3);
        CP_COMMIT();
        CP_WAIT2();
        __syncthreads();
        comp(kt % 3);
        __syncthreads();
    }

    // ---------------- epilogue ----------------
    const float inv127 = 1.f / 127.f;
    int Mv = counts ? counts[e] : (1 << 30);
    int c_base = n0 + wn * 32 + (lane & 3) * 2;

    float sb_v[8];
#pragma unroll
    for (int nf = 0; nf < 4; nf++) {
        sb_v[nf * 2]     = sb_arr[(size_t)e * sb_estride + c_base + nf * 8];
        sb_v[nf * 2 + 1] = sb_arr[(size_t)e * sb_estride + c_base + nf * 8 + 1];
    }

#pragma unroll
    for (int mt = 0; mt < 2; mt++) {
#pragma unroll
        for (int half = 0; half < 2; half++) {
            int r = m0 + wm * 32 + mt * 16 + (lane >> 2) + half * 8;
            int sa_idx = arowidx ? arowidx[e * CAP + r] : r;
            float sa = sa_arr[(size_t)e * sa_estride + sa_idx];
            if (outf) {
                float* orow = outf + (size_t)e * o_estride + (size_t)r * ldo;
#pragma unroll
                for (int nf = 0; nf < 4; nf++) {
                    int c = c_base + nf * 8;
                    float v0 = sa * sb_v[nf*2]   * ((float)hh[mt][nf][half*2]   + (float)hl[mt][nf][half*2]   * inv127);
                    float v1 = sa * sb_v[nf*2+1] * ((float)hh[mt][nf][half*2+1] + (float)hl[mt][nf][half*2+1] * inv127);
                    orow[c]     = v0;
                    orow[c + 1] = v1;
                }
            } else if (r < Mv) {
                int tok = scatidx ? scatidx[e * CAP + r] : r;
                float w = wts ? wts[e * CAP + r] : 1.f;
                float* orow = outscat + (size_t)tok * ldo;
#pragma unroll
                for (int nf = 0; nf < 4; nf++) {
                    int c = c_base + nf * 8;
                    float v0 = w * sa * sb_v[nf*2]   * ((float)hh[mt][nf][half*2]   + (float)hl[mt][nf][half*2]   * inv127);
                    float v1 = w * sa * sb_v[nf*2+1] * ((float)hh[mt][nf][half*2+1] + (float)hl[mt][nf][half*2+1] * inv127);
                    if (accumulate) {
                        atomicAdd(&orow[c],     v0);
                        atomicAdd(&orow[c + 1], v1);
                    } else {
                        orow[c]     = v0;
                        orow[c + 1] = v1;
                    }
                }
            }
        }
    }
}

// ---------------- launch ----------------
extern "C" void kernel_launch(void* const* d_in, const int* in_sizes, int n_in,
                              void* d_out, int out_size)
{
    const float* x       = (const float*)d_in[0];
    const float* gate_w  = (const float*)d_in[1];
    const float* we_gate = (const float*)d_in[2];
    const float* we_up   = (const float*)d_in[3];
    const float* we_down = (const float*)d_in[4];
    const float* ws_gate = (const float*)d_in[5];
    const float* ws_up   = (const float*)d_in[6];
    const float* ws_down = (const float*)d_in[7];
    float* out = (float*)d_out;

    cudaFuncSetAttribute(gemm_s8_kernel, cudaFuncAttributeMaxDynamicSharedMemorySize, 3 * STG_B);

    int8_t *xh, *xl, *wgh, *wgl, *wuh, *wul, *wdh, *wdl;
    int8_t *sgh, *sgl, *suh, *sul, *sdh, *sdl, *arh, *arl, *ash, *asl;
    float *sx, *swg, *swu, *swd, *ssg, *ssu, *ssd, *sar, *sas;
    float *grf, *urf, *gsf, *usf, *ewt;
    int *etok, *counts;
    cudaGetSymbolAddress((void**)&xh, g_xh);   cudaGetSymbolAddress((void**)&xl, g_xl);
    cudaGetSymbolAddress((void**)&wgh, g_wgh); cudaGetSymbolAddress((void**)&wgl, g_wgl);
    cudaGetSymbolAddress((void**)&wuh, g_wuh); cudaGetSymbolAddress((void**)&wul, g_wul);
    cudaGetSymbolAddress((void**)&wdh, g_wdh); cudaGetSymbolAddress((void**)&wdl, g_wdl);
    cudaGetSymbolAddress((void**)&sgh, g_sgh); cudaGetSymbolAddress((void**)&sgl, g_sgl);
    cudaGetSymbolAddress((void**)&suh, g_suh); cudaGetSymbolAddress((void**)&sul, g_sul);
    cudaGetSymbolAddress((void**)&sdh, g_sdh); cudaGetSymbolAddress((void**)&sdl, g_sdl);
    cudaGetSymbolAddress((void**)&arh, g_arh); cudaGetSymbolAddress((void**)&arl, g_arl);
    cudaGetSymbolAddress((void**)&ash, g_ash); cudaGetSymbolAddress((void**)&asl, g_asl);
    cudaGetSymbolAddress((void**)&sx, g_sx);   cudaGetSymbolAddress((void**)&swg, g_swg);
    cudaGetSymbolAddress((void**)&swu, g_swu); cudaGetSymbolAddress((void**)&swd, g_swd);
    cudaGetSymbolAddress((void**)&ssg, g_ssg); cudaGetSymbolAddress((void**)&ssu, g_ssu);
    cudaGetSymbolAddress((void**)&ssd, g_ssd); cudaGetSymbolAddress((void**)&sar, g_sar);
    cudaGetSymbolAddress((void**)&sas, g_sas);
    cudaGetSymbolAddress((void**)&grf, g_gr);  cudaGetSymbolAddress((void**)&urf, g_ur);
    cudaGetSymbolAddress((void**)&gsf, g_gs);  cudaGetSymbolAddress((void**)&usf, g_us);
    cudaGetSymbolAddress((void**)&etok, g_etok);
    cudaGetSymbolAddress((void**)&ewt,  g_ewt);
    cudaGetSymbolAddress((void**)&counts, g_counts);

    // 1: quantize x + all weights (37888 warp-rows)
    quant_all_kernel<<<4736, 256>>>(x, we_gate, we_up, we_down, ws_gate, ws_up, ws_down);
    // 2, 3: router + capacity scan
    router_kernel<<<NTOK / 8, 256>>>(x, gate_w);
    scan_kernel<<<1, 256>>>();

    // 4: shared gate GEMM -> g_gs
    gemm_s8_kernel<<<dim3(SHI / 64, NTOK / 128, 1), 256, 3 * STG_B>>>(
        xh, xl, HDIM, 0, nullptr,
        sgh, sgl, 0, sx, 0, ssg, 0,
        gsf, 0, SHI, nullptr, nullptr, nullptr, 0, nullptr, HDIM);
    // 5: shared up GEMM -> g_us
    gemm_s8_kernel<<<dim3(SHI / 64, NTOK / 128, 1), 256, 3 * STG_B>>>(
        xh, xl, HDIM, 0, nullptr,
        suh, sul, 0, sx, 0, ssu, 0,
        usf, 0, SHI, nullptr, nullptr, nullptr, 0, nullptr, HDIM);
    // 6 (ncu target): routed gate GEMM -> g_gr
    gemm_s8_kernel<<<dim3(IDIM / 64, CAP / 128, NEXP), 256, 3 * STG_B>>>(
        xh, xl, HDIM, 0, etok,
        wgh, wgl, (size_t)IDIM * HDIM, sx, 0, swg, IDIM,
        grf, (size_t)CAP * IDIM, IDIM, nullptr, nullptr, nullptr, 0, counts, HDIM);
    // 7: routed up GEMM -> g_ur
    gemm_s8_kernel<<<dim3(IDIM / 64, CAP / 128, NEXP), 256, 3 * STG_B>>>(
        xh, xl, HDIM, 0, etok,
        wuh, wul, (size_t)IDIM * HDIM, sx, 0, swu, IDIM,
        urf, (size_t)CAP * IDIM, IDIM, nullptr, nullptr, nullptr, 0, counts, HDIM);

    // 8: SwiGLU + activation quantization (28672 warp-rows)
    act_quant_kernel<<<3584, 256>>>();

    // 9: shared down GEMM -> writes d_out (initializes poisoned buffer)
    gemm_s8_kernel<<<dim3(HDIM / 64, NTOK / 128, 1), 256, 3 * STG_B>>>(
        ash, asl, SHI, 0, nullptr,
        sdh, sdl, 0, sas, 0, ssd, 0,
        nullptr, 0, HDIM, out, nullptr, nullptr, 0, nullptr, SHI);
    // 10: routed down GEMM -> weighted atomic scatter into d_out
    gemm_s8_kernel<<<dim3(HDIM / 64, CAP / 128, NEXP), 256, 3 * STG_B>>>(
        arh, arl, IDIM, (size_t)CAP * IDIM, nullptr,
        wdh, wdl, (size_t)HDIM * IDIM, sar, CAP, swd, HDIM,
        nullptr, 0, HDIM, out, etok, ewt, 1, counts, IDIM);
}

// round 9
// speedup vs baseline: 2.6146x; 2.6146x over previous
#include <cuda_runtime.h>
#include <cuda_bf16.h>
#include <cstdint>
#include <cstddef>

#define NTOK 8192
#define HDIM 1024
#define NEXP 8
#define TOPK 2
#define IDIM 1024
#define SHI  2048
#define CAP  2560   // ceil(1.25 * 8192 * 2 / 8)

typedef __nv_bfloat16 bf16;

// ---------------- device scratch ----------------
__device__ int   g_topk_idx[NTOK * TOPK];
__device__ float g_topk_w[NTOK * TOPK];
__device__ int   g_etok[NEXP * CAP];
__device__ float g_ewt[NEXP * CAP];
__device__ int   g_counts[NEXP];

__device__ __align__(128) bf16 g_x_h[NTOK * HDIM], g_x_l[NTOK * HDIM];
__device__ __align__(128) bf16 g_wg_h[NEXP * IDIM * HDIM], g_wg_l[NEXP * IDIM * HDIM];
__device__ __align__(128) bf16 g_wu_h[NEXP * IDIM * HDIM], g_wu_l[NEXP * IDIM * HDIM];
__device__ __align__(128) bf16 g_wd_h[NEXP * HDIM * IDIM], g_wd_l[NEXP * HDIM * IDIM];
__device__ __align__(128) bf16 g_sg_h[SHI * HDIM], g_sg_l[SHI * HDIM];
__device__ __align__(128) bf16 g_su_h[SHI * HDIM], g_su_l[SHI * HDIM];
__device__ __align__(128) bf16 g_sd_h[HDIM * SHI], g_sd_l[HDIM * SHI];
__device__ __align__(128) bf16 g_ar_h[(size_t)NEXP * CAP * IDIM], g_ar_l[(size_t)NEXP * CAP * IDIM];
__device__ __align__(128) bf16 g_as_h[(size_t)NTOK * SHI], g_as_l[(size_t)NTOK * SHI];

__device__ __forceinline__ float silu_f(float x) { return x / (1.f + __expf(-x)); }
__device__ __forceinline__ uint32_t sw64(uint32_t b) { return b ^ ((b >> 3) & 0x30); }

__device__ __forceinline__ void cp16(uint32_t dst, const void* src) {
    asm volatile("cp.async.cg.shared.global [%0], [%1], 16;" :: "r"(dst), "l"(src));
}
#define CP_COMMIT() asm volatile("cp.async.commit_group;")
#define CP_WAIT1()  asm volatile("cp.async.wait_group 1;")
#define CP_WAIT0()  asm volatile("cp.async.wait_group 0;")

__device__ __forceinline__ void ldsm4(uint32_t* r, uint32_t addr) {
    asm volatile("ldmatrix.sync.aligned.m8n8.x4.shared.b16 {%0,%1,%2,%3}, [%4];"
                 : "=r"(r[0]), "=r"(r[1]), "=r"(r[2]), "=r"(r[3]) : "r"(addr));
}

__device__ __forceinline__ void mma_bf16(float (&c)[4], const uint32_t (&a)[4],
                                         uint32_t b0, uint32_t b1)
{
    asm volatile(
        "mma.sync.aligned.m16n8k16.row.col.f32.bf16.bf16.f32 "
        "{%0,%1,%2,%3}, {%4,%5,%6,%7}, {%8,%9}, {%0,%1,%2,%3};\n"
        : "+f"(c[0]), "+f"(c[1]), "+f"(c[2]), "+f"(c[3])
        : "r"(a[0]), "r"(a[1]), "r"(a[2]), "r"(a[3]), "r"(b0), "r"(b1));
}

__device__ __forceinline__ void store_pair(bf16* hi, bf16* lo, size_t off, float v0, float v1) {
    bf16 h0 = __float2bfloat16(v0), h1 = __float2bfloat16(v1);
    bf16 l0 = __float2bfloat16(v0 - __bfloat162float(h0));
    bf16 l1 = __float2bfloat16(v1 - __bfloat162float(h1));
    *reinterpret_cast<__nv_bfloat162*>(hi + off) = __halves2bfloat162(h0, h1);
    *reinterpret_cast<__nv_bfloat162*>(lo + off) = __halves2bfloat162(l0, l1);
}

// ---------------- fused fp32 -> bf16 hi/lo conversion ----------------
__device__ __forceinline__ void cvt4(const float* s, bf16* h, bf16* l, size_t i) {
    float4 v = *(const float4*)(s + i);
    store_pair(h, l, i,     v.x, v.y);
    store_pair(h, l, i + 2, v.z, v.w);
}

__global__ void convert_all_kernel(
    const float* __restrict__ x,  const float* __restrict__ wg,
    const float* __restrict__ wu, const float* __restrict__ wd,
    const float* __restrict__ sg, const float* __restrict__ su,
    const float* __restrict__ sd)
{
    size_t g = (size_t)blockIdx.x * 256 + threadIdx.x;
    const size_t GB = 2097152;   // 8.39M elems / 4
    const size_t GS = 524288;    // 2.10M elems / 4
    if (g < GB) { cvt4(x,  g_x_h,  g_x_l,  g * 4); return; }
    g -= GB;
    if (g < GB) { cvt4(wg, g_wg_h, g_wg_l, g * 4); return; }
    g -= GB;
    if (g < GB) { cvt4(wu, g_wu_h, g_wu_l, g * 4); return; }
    g -= GB;
    if (g < GB) { cvt4(wd, g_wd_h, g_wd_l, g * 4); return; }
    g -= GB;
    if (g < GS) { cvt4(sg, g_sg_h, g_sg_l, g * 4); return; }
    g -= GS;
    if (g < GS) { cvt4(su, g_su_h, g_su_l, g * 4); return; }
    g -= GS;
    if (g < GS) { cvt4(sd, g_sd_h, g_sd_l, g * 4); return; }
}

// ---------------- router ----------------
__global__ void router_kernel(const float* __restrict__ x, const float* __restrict__ gw)
{
    int warp = threadIdx.x >> 5;
    int lane = threadIdx.x & 31;
    int tok  = blockIdx.x * 8 + warp;
    if (tok >= NTOK) return;
    const float* xr = x + (size_t)tok * HDIM;

    float acc[NEXP];
#pragma unroll
    for (int e = 0; e < NEXP; e++) acc[e] = 0.f;
    for (int h = lane; h < HDIM; h += 32) {
        float xv = xr[h];
#pragma unroll
        for (int e = 0; e < NEXP; e++) acc[e] += xv * gw[e * HDIM + h];
    }
#pragma unroll
    for (int e = 0; e < NEXP; e++) {
#pragma unroll
        for (int off = 16; off > 0; off >>= 1)
            acc[e] += __shfl_xor_sync(0xffffffffu, acc[e], off);
    }
    if (lane == 0) {
        float mx = acc[0];
#pragma unroll
        for (int e = 1; e < NEXP; e++) mx = fmaxf(mx, acc[e]);
        float p[NEXP]; float s = 0.f;
#pragma unroll
        for (int e = 0; e < NEXP; e++) { p[e] = expf(acc[e] - mx); s += p[e]; }
#pragma unroll
        for (int e = 0; e < NEXP; e++) p[e] /= s;
        int i0 = 0;
#pragma unroll
        for (int e = 1; e < NEXP; e++) if (p[e] > p[i0]) i0 = e;
        int i1 = -1;
#pragma unroll
        for (int e = 0; e < NEXP; e++) {
            if (e == i0) continue;
            if (i1 < 0 || p[e] > p[i1]) i1 = e;
        }
        float w0 = p[i0], w1 = p[i1];
        float inv = 1.f / (w0 + w1 + 1e-20f);
        g_topk_idx[tok * 2 + 0] = i0;
        g_topk_idx[tok * 2 + 1] = i1;
        g_topk_w[tok * 2 + 0] = w0 * inv;
        g_topk_w[tok * 2 + 1] = w1 * inv;
    }
}

// ---------------- capacity scan + compaction (reference order) ----------------
__global__ void scan_kernel()
{
    __shared__ int hist[256][NEXP];
    int t = threadIdx.x;
    const int per = (NTOK * TOPK) / 256;
    int local[NEXP];
#pragma unroll
    for (int e = 0; e < NEXP; e++) local[e] = 0;
    int base = t * per;
    for (int i = 0; i < per; i++) local[g_topk_idx[base + i]]++;
#pragma unroll
    for (int e = 0; e < NEXP; e++) hist[t][e] = local[e];
    __syncthreads();
    if (t < NEXP) {
        int run = 0;
        for (int i = 0; i < 256; i++) { int v = hist[i][t]; hist[i][t] = run; run += v; }
        g_counts[t] = run < CAP ? run : CAP;
    }
    __syncthreads();
    int off[NEXP];
#pragma unroll
    for (int e = 0; e < NEXP; e++) off[e] = hist[t][e];
    for (int i = 0; i < per; i++) {
        int slot = base + i;
        int e = g_topk_idx[slot];
        int pos = off[e]++;
        if (pos < CAP) {
            g_etok[e * CAP + pos] = slot >> 1;
            g_ewt[e * CAP + pos]  = g_topk_w[slot];
        }
    }
}

// ============================================================================
// GLU GEMM (R4 skeleton): O = silu(A@G^T)*(A@U^T) -> bf16 hi/lo
// CTA 128x64, BK=32, 2-stage cp.async ring, 256 threads, 2 CTAs/SM.
// ============================================================================
#define GSTG 32768   // per stage: Ah 8K | Al 8K | Gh 4K | Gl 4K | Uh 4K | Ul 4K

__global__ __launch_bounds__(256, 2) void glu_bf16_kernel(
    const bf16* __restrict__ Ahi, const bf16* __restrict__ Alo, int lda,
    const int* __restrict__ rowidx,
    const bf16* __restrict__ Ghi_, const bf16* __restrict__ Glo_,
    const bf16* __restrict__ Uhi_, const bf16* __restrict__ Ulo_, size_t bstride,
    bf16* __restrict__ Ohi_, bf16* __restrict__ Olo_, size_t ostride, int ldo,
    int Kdim, const int* __restrict__ counts)
{
    extern __shared__ __align__(128) char smdyn[];
    const int e = blockIdx.z;
    const int m0 = blockIdx.y * 128, n0 = blockIdx.x * 64;
    if (counts && m0 >= counts[e]) return;

    const char* Gh = (const char*)(Ghi_ + (size_t)e * bstride);
    const char* Gl = (const char*)(Glo_ + (size_t)e * bstride);
    const char* Uh = (const char*)(Uhi_ + (size_t)e * bstride);
    const char* Ul = (const char*)(Ulo_ + (size_t)e * bstride);
    bf16* Oh = Ohi_ + (size_t)e * ostride;
    bf16* Ol = Olo_ + (size_t)e * ostride;
    const int* ridx = rowidx ? rowidx + e * CAP : nullptr;

    const int tid = threadIdx.x;
    uint32_t smb = (uint32_t)__cvta_generic_to_shared(smdyn);
    const int AH = 0, AL = 8192, GHo = 16384, GLo = 20480, UHo = 24576, ULo = 28672;

    int ar0 = tid >> 2, ac = tid & 3;          // A rows 0..63, 16B chunk 0..3
    int ar1 = ar0 + 64;
    int tok0 = ridx ? ridx[m0 + ar0] : m0 + ar0;
    int tok1 = ridx ? ridx[m0 + ar1] : m0 + ar1;
    size_t ab0 = ((size_t)tok0 * lda + ac * 8) * 2;
    size_t ab1 = ((size_t)tok1 * lda + ac * 8) * 2;
    size_t bb  = ((size_t)(n0 + ar0) * Kdim + ac * 8) * 2;
    uint32_t dA0 = sw64(ar0 * 64 + ac * 16);
    uint32_t dA1 = sw64(ar1 * 64 + ac * 16);
    const char* pAh = (const char*)Ahi;
    const char* pAl = (const char*)Alo;

    auto load_stage = [&](int kt, int buf) {
        uint32_t s = smb + (uint32_t)buf * GSTG;
        long kb = (long)kt * 64;          // 32 elems * 2B
        cp16(s + AH + dA0, pAh + ab0 + kb);
        cp16(s + AH + dA1, pAh + ab1 + kb);
        cp16(s + AL + dA0, pAl + ab0 + kb);
        cp16(s + AL + dA1, pAl + ab1 + kb);
        cp16(s + GHo + dA0, Gh + bb + kb);
        cp16(s + GLo + dA0, Gl + bb + kb);
        cp16(s + UHo + dA0, Uh + bb + kb);
        cp16(s + ULo + dA0, Ul + bb + kb);
    };

    const int lane = tid & 31, warp = tid >> 5;
    const int wm = warp & 3, wn = warp >> 2;
    const int lr = lane & 15, lc = (lane >> 4) * 16;

    float accG[2][4][4], accU[2][4][4];
#pragma unroll
    for (int mt = 0; mt < 2; mt++)
#pragma unroll
        for (int nf = 0; nf < 4; nf++)
#pragma unroll
            for (int i = 0; i < 4; i++) { accG[mt][nf][i] = 0.f; accU[mt][nf][i] = 0.f; }

    auto comp_stage = [&](int buf) {
        uint32_t s = smb + (uint32_t)buf * GSTG;
#pragma unroll
        for (int kk = 0; kk < 2; kk++) {
            uint32_t ah[2][4], al[2][4];
#pragma unroll
            for (int mt = 0; mt < 2; mt++) {
                uint32_t o = sw64((wm * 32 + mt * 16 + lr) * 64 + kk * 32 + lc);
                ldsm4(ah[mt], s + AH + o);
                ldsm4(al[mt], s + AL + o);
            }
            uint32_t bgh[2][4], bgl[2][4], buh[2][4], bul[2][4];
#pragma unroll
            for (int nt = 0; nt < 2; nt++) {
                uint32_t o = sw64((wn * 32 + nt * 16 + lr) * 64 + kk * 32 + lc);
                ldsm4(bgh[nt], s + GHo + o);
                ldsm4(bgl[nt], s + GLo + o);
                ldsm4(buh[nt], s + UHo + o);
                ldsm4(bul[nt], s + ULo + o);
            }
#pragma unroll
            for (int mt = 0; mt < 2; mt++) {
#pragma unroll
                for (int nf = 0; nf < 4; nf++) {
                    int nt = nf >> 1, sb = nf & 1;
                    mma_bf16(accG[mt][nf], ah[mt], bgh[nt][sb], bgh[nt][sb + 2]);
                    mma_bf16(accG[mt][nf], ah[mt], bgl[nt][sb], bgl[nt][sb + 2]);
                    mma_bf16(accG[mt][nf], al[mt], bgh[nt][sb], bgh[nt][sb + 2]);
                    mma_bf16(accU[mt][nf], ah[mt], buh[nt][sb], buh[nt][sb + 2]);
                    mma_bf16(accU[mt][nf], ah[mt], bul[nt][sb], bul[nt][sb + 2]);
                    mma_bf16(accU[mt][nf], al[mt], buh[nt][sb], buh[nt][sb + 2]);
                }
            }
        }
    };

    // ---- 2-stage pipeline (R4 double-sync discipline) ----
    const int KT = Kdim >> 5;
    load_stage(0, 0); CP_COMMIT();
    for (int kt = 0; kt < KT; kt++) {
        if (kt + 1 < KT) {
            load_stage(kt + 1, (kt + 1) & 1);
            CP_COMMIT();
            CP_WAIT1();
        } else {
            CP_WAIT0();
        }
        __syncthreads();
        comp_stage(kt & 1);
        __syncthreads();
    }

    // ---- epilogue: silu(g)*u -> bf16 hi/lo ----
    int r0e = m0 + wm * 32 + (lane >> 2);
    int c0e = n0 + wn * 32 + (lane & 3) * 2;
#pragma unroll
    for (int mt = 0; mt < 2; mt++) {
#pragma unroll
        for (int nf = 0; nf < 4; nf++) {
            int r = r0e + mt * 16;
            int c = c0e + nf * 8;
            float v0 = silu_f(accG[mt][nf][0]) * accU[mt][nf][0];
            float v1 = silu_f(accG[mt][nf][1]) * accU[mt][nf][1];
            float v2 = silu_f(accG[mt][nf][2]) * accU[mt][nf][2];
            float v3 = silu_f(accG[mt][nf][3]) * accU[mt][nf][3];
            store_pair(Oh, Ol, (size_t)r * ldo + c, v0, v1);
            store_pair(Oh, Ol, (size_t)(r + 8) * ldo + c, v2, v3);
        }
    }
}

// ============================================================================
// Down GEMM (R4 skeleton): out[tok,n] (+)= w * (A@B^T), fp32 out
// CTA 128x64, BK=32, 2-stage ring, 256 threads, 2 CTAs/SM.
// ============================================================================
#define DSTG 24576   // per stage: Ah 8K | Al 8K | Bh 4K | Bl 4K

__global__ __launch_bounds__(256, 2) void down_bf16_kernel(
    const bf16* __restrict__ Ahi_, const bf16* __restrict__ Alo_, int lda, size_t astride,
    const bf16* __restrict__ Bhi_, const bf16* __restrict__ Blo_, size_t bstride,
    const int* __restrict__ rowidx, const float* __restrict__ wts,
    const int* __restrict__ counts, int Mtotal,
    float* __restrict__ out, int ldo, int Kdim, int accumulate)
{
    extern __shared__ __align__(128) char smdyn[];
    const int e = blockIdx.z;
    const int m0 = blockIdx.y * 128, n0 = blockIdx.x * 64;
    if (counts && m0 >= counts[e]) return;

    const char* pAh = (const char*)(Ahi_ + (size_t)e * astride);
    const char* pAl = (const char*)(Alo_ + (size_t)e * astride);
    const char* pBh = (const char*)(Bhi_ + (size_t)e * bstride);
    const char* pBl = (const char*)(Blo_ + (size_t)e * bstride);

    const int tid = threadIdx.x;
    uint32_t smb = (uint32_t)__cvta_generic_to_shared(smdyn);
    const int AH = 0, AL = 8192, BH = 16384, BL = 20480;

    int ar0 = tid >> 2, ac = tid & 3;
    int ar1 = ar0 + 64;
    size_t ab0 = ((size_t)(m0 + ar0) * lda + ac * 8) * 2;
    size_t ab1 = ((size_t)(m0 + ar1) * lda + ac * 8) * 2;
    size_t bb  = ((size_t)(n0 + ar0) * Kdim + ac * 8) * 2;
    uint32_t dA0 = sw64(ar0 * 64 + ac * 16);
    uint32_t dA1 = sw64(ar1 * 64 + ac * 16);

    auto load_stage = [&](int kt, int buf) {
        uint32_t s = smb + (uint32_t)buf * DSTG;
        long kb = (long)kt * 64;
        cp16(s + AH + dA0, pAh + ab0 + kb);
        cp16(s + AH + dA1, pAh + ab1 + kb);
        cp16(s + AL + dA0, pAl + ab0 + kb);
        cp16(s + AL + dA1, pAl + ab1 + kb);
        cp16(s + BH + dA0, pBh + bb + kb);
        cp16(s + BL + dA0, pBl + bb + kb);
    };

    const int lane = tid & 31, warp = tid >> 5;
    const int wm = warp & 3, wn = warp >> 2;
    const int lr = lane & 15, lc = (lane >> 4) * 16;

    float acc[2][4][4];
#pragma unroll
    for (int mt = 0; mt < 2; mt++)
#pragma unroll
        for (int nf = 0; nf < 4; nf++)
#pragma unroll
            for (int i = 0; i < 4; i++) acc[mt][nf][i] = 0.f;

    auto comp_stage = [&](int buf) {
        uint32_t s = smb + (uint32_t)buf * DSTG;
#pragma unroll
        for (int kk = 0; kk < 2; kk++) {
            uint32_t ah[2][4], al[2][4];
#pragma unroll
            for (int mt = 0; mt < 2; mt++) {
                uint32_t o = sw64((wm * 32 + mt * 16 + lr) * 64 + kk * 32 + lc);
                ldsm4(ah[mt], s + AH + o);
                ldsm4(al[mt], s + AL + o);
            }
            uint32_t bh[2][4], bl[2][4];
#pragma unroll
            for (int nt = 0; nt < 2; nt++) {
                uint32_t o = sw64((wn * 32 + nt * 16 + lr) * 64 + kk * 32 + lc);
                ldsm4(bh[nt], s + BH + o);
                ldsm4(bl[nt], s + BL + o);
            }
#pragma unroll
            for (int mt = 0; mt < 2; mt++) {
#pragma unroll
                for (int nf = 0; nf < 4; nf++) {
                    int nt = nf >> 1, sb = nf & 1;
                    mma_bf16(acc[mt][nf], ah[mt], bh[nt][sb], bh[nt][sb + 2]);
                    mma_bf16(acc[mt][nf], ah[mt], bl[nt][sb], bl[nt][sb + 2]);
                    mma_bf16(acc[mt][nf], al[mt], bh[nt][sb], bh[nt][sb + 2]);
                }
            }
        }
    };

    const int KT = Kdim >> 5;
    load_stage(0, 0); CP_COMMIT();
    for (int kt = 0; kt < KT; kt++) {
        if (kt + 1 < KT) {
            load_stage(kt + 1, (kt + 1) & 1);
            CP_COMMIT();
            CP_WAIT1();
        } else {
            CP_WAIT0();
        }
        __syncthreads();
        comp_stage(kt & 1);
        __syncthreads();
    }

    int Mv = counts ? counts[e] : Mtotal;
#pragma unroll
    for (int mt = 0; mt < 2; mt++) {
#pragma unroll
        for (int nf = 0; nf < 4; nf++) {
            int colg = n0 + wn * 32 + nf * 8 + (lane & 3) * 2;
            int r0 = m0 + wm * 32 + mt * 16 + (lane >> 2);
#pragma unroll
            for (int half = 0; half < 2; half++) {
                int r = r0 + half * 8;
                if (r < Mv) {
                    int tok; float w;
                    if (rowidx) { tok = rowidx[e * CAP + r]; w = wts[e * CAP + r]; }
                    else        { tok = r; w = 1.f; }
                    float v0 = acc[mt][nf][half * 2 + 0] * w;
                    float v1 = acc[mt][nf][half * 2 + 1] * w;
                    if (accumulate) {
                        atomicAdd(&out[(size_t)tok * ldo + colg],     v0);
                        atomicAdd(&out[(size_t)tok * ldo + colg + 1], v1);
                    } else {
                        out[(size_t)tok * ldo + colg]     = v0;
                        out[(size_t)tok * ldo + colg + 1] = v1;
                    }
                }
            }
        }
    }
}

// ---------------- launch ----------------
extern "C" void kernel_launch(void* const* d_in, const int* in_sizes, int n_in,
                              void* d_out, int out_size)
{
    const float* x       = (const float*)d_in[0];
    const float* gate_w  = (const float*)d_in[1];
    const float* we_gate = (const float*)d_in[2];
    const float* we_up   = (const float*)d_in[3];
    const float* we_down = (const float*)d_in[4];
    const float* ws_gate = (const float*)d_in[5];
    const float* ws_up   = (const float*)d_in[6];
    const float* ws_down = (const float*)d_in[7];
    float* out = (float*)d_out;

    cudaFuncSetAttribute(glu_bf16_kernel,  cudaFuncAttributeMaxDynamicSharedMemorySize, 2 * GSTG);
    cudaFuncSetAttribute(down_bf16_kernel, cudaFuncAttributeMaxDynamicSharedMemorySize, 2 * DSTG);

    bf16 *x_h, *x_l, *wg_h, *wg_l, *wu_h, *wu_l, *wd_h, *wd_l;
    bf16 *sg_h, *sg_l, *su_h, *su_l, *sd_h, *sd_l;
    bf16 *ar_h, *ar_l, *as_h, *as_l;
    int *etok, *counts; float *ewt;
    cudaGetSymbolAddress((void**)&x_h, g_x_h);   cudaGetSymbolAddress((void**)&x_l, g_x_l);
    cudaGetSymbolAddress((void**)&wg_h, g_wg_h); cudaGetSymbolAddress((void**)&wg_l, g_wg_l);
    cudaGetSymbolAddress((void**)&wu_h, g_wu_h); cudaGetSymbolAddress((void**)&wu_l, g_wu_l);
    cudaGetSymbolAddress((void**)&wd_h, g_wd_h); cudaGetSymbolAddress((void**)&wd_l, g_wd_l);
    cudaGetSymbolAddress((void**)&sg_h, g_sg_h); cudaGetSymbolAddress((void**)&sg_l, g_sg_l);
    cudaGetSymbolAddress((void**)&su_h, g_su_h); cudaGetSymbolAddress((void**)&su_l, g_su_l);
    cudaGetSymbolAddress((void**)&sd_h, g_sd_h); cudaGetSymbolAddress((void**)&sd_l, g_sd_l);
    cudaGetSymbolAddress((void**)&ar_h, g_ar_h); cudaGetSymbolAddress((void**)&ar_l, g_ar_l);
    cudaGetSymbolAddress((void**)&as_h, g_as_h); cudaGetSymbolAddress((void**)&as_l, g_as_l);
    cudaGetSymbolAddress((void**)&etok, g_etok);
    cudaGetSymbolAddress((void**)&ewt,  g_ewt);
    cudaGetSymbolAddress((void**)&counts, g_counts);

    // 1: fused conversion
    convert_all_kernel<<<38912, 256>>>(x, we_gate, we_up, we_down, ws_gate, ws_up, ws_down);
    // 2, 3: router + capacity scan
    router_kernel<<<NTOK / 8, 256>>>(x, gate_w);
    scan_kernel<<<1, 256>>>();

    // 4: shared gate/up + SwiGLU -> g_as
    glu_bf16_kernel<<<dim3(SHI / 64, NTOK / 128, 1), 256, 2 * GSTG>>>(
        x_h, x_l, HDIM, nullptr,
        sg_h, sg_l, su_h, su_l, 0,
        as_h, as_l, 0, SHI, HDIM, nullptr);

    // 5: shared down-proj (initializes poisoned out)
    down_bf16_kernel<<<dim3(HDIM / 64, NTOK / 128, 1), 256, 2 * DSTG>>>(
        as_h, as_l, SHI, 0,
        sd_h, sd_l, 0,
        nullptr, nullptr, nullptr, NTOK,
        out, HDIM, SHI, /*accumulate=*/0);

    // 6 (ncu capture slot): routed gate/up + SwiGLU -> g_ar
    glu_bf16_kernel<<<dim3(IDIM / 64, CAP / 128, NEXP), 256, 2 * GSTG>>>(
        x_h, x_l, HDIM, etok,
        wg_h, wg_l, wu_h, wu_l, (size_t)IDIM * HDIM,
        ar_h, ar_l, (size_t)CAP * IDIM, IDIM, HDIM, counts);

    // 7: routed down-proj, weighted atomic scatter
    down_bf16_kernel<<<dim3(HDIM / 64, CAP / 128, NEXP), 256, 2 * DSTG>>>(
        ar_h, ar_l, IDIM, (size_t)CAP * IDIM,
        wd_h, wd_l, (size_t)HDIM * IDIM,
        etok, ewt, counts, 0,
        out, HDIM, IDIM, /*accumulate=*/1);
}

// round 10
// speedup vs baseline: 3.5992x; 1.3766x over previous
#include <cuda_runtime.h>
#include <cuda_fp16.h>
#include <cstdint>
#include <cstddef>

#define NTOK 8192
#define HDIM 1024
#define NEXP 8
#define TOPK 2
#define IDIM 1024
#define SHI  2048
#define CAP  2560   // ceil(1.25 * 8192 * 2 / 8)

// ---------------- device scratch ----------------
__device__ int   g_topk_idx[NTOK * TOPK];
__device__ float g_topk_w[NTOK * TOPK];
__device__ int   g_etok[NEXP * CAP];
__device__ float g_ewt[NEXP * CAP];
__device__ int   g_counts[NEXP];

// A-side operands: fp16 hi/lo (22-bit effective). B-side: single fp16.
__device__ __align__(128) __half g_x_h[NTOK * HDIM], g_x_l[NTOK * HDIM];
__device__ __align__(128) __half g_wg[NEXP * IDIM * HDIM];
__device__ __align__(128) __half g_wu[NEXP * IDIM * HDIM];
__device__ __align__(128) __half g_wd[NEXP * HDIM * IDIM];
__device__ __align__(128) __half g_sg[SHI * HDIM];
__device__ __align__(128) __half g_su[SHI * HDIM];
__device__ __align__(128) __half g_sd[HDIM * SHI];
__device__ __align__(128) __half g_ar_h[(size_t)NEXP * CAP * IDIM], g_ar_l[(size_t)NEXP * CAP * IDIM];
__device__ __align__(128) __half g_as_h[(size_t)NTOK * SHI], g_as_l[(size_t)NTOK * SHI];

__device__ __forceinline__ float silu_f(float x) { return x / (1.f + __expf(-x)); }
__device__ __forceinline__ uint32_t sw64(uint32_t b) { return b ^ ((b >> 3) & 0x30); }

__device__ __forceinline__ void cp16(uint32_t dst, const void* src) {
    asm volatile("cp.async.cg.shared.global [%0], [%1], 16;" :: "r"(dst), "l"(src));
}
#define CP_COMMIT() asm volatile("cp.async.commit_group;")
#define CP_WAIT1()  asm volatile("cp.async.wait_group 1;")
#define CP_WAIT0()  asm volatile("cp.async.wait_group 0;")

__device__ __forceinline__ void ldsm4(uint32_t* r, uint32_t addr) {
    asm volatile("ldmatrix.sync.aligned.m8n8.x4.shared.b16 {%0,%1,%2,%3}, [%4];"
                 : "=r"(r[0]), "=r"(r[1]), "=r"(r[2]), "=r"(r[3]) : "r"(addr));
}

__device__ __forceinline__ void mma_f16(float (&c)[4], const uint32_t (&a)[4],
                                        uint32_t b0, uint32_t b1)
{
    asm volatile(
        "mma.sync.aligned.m16n8k16.row.col.f32.f16.f16.f32 "
        "{%0,%1,%2,%3}, {%4,%5,%6,%7}, {%8,%9}, {%0,%1,%2,%3};\n"
        : "+f"(c[0]), "+f"(c[1]), "+f"(c[2]), "+f"(c[3])
        : "r"(a[0]), "r"(a[1]), "r"(a[2]), "r"(a[3]), "r"(b0), "r"(b1));
}

__device__ __forceinline__ void store_pair_h(__half* hi, __half* lo, size_t off,
                                             float v0, float v1) {
    __half h0 = __float2half(v0), h1 = __float2half(v1);
    __half l0 = __float2half(v0 - __half2float(h0));
    __half l1 = __float2half(v1 - __half2float(h1));
    *reinterpret_cast<__half2*>(hi + off) = __halves2half2(h0, h1);
    *reinterpret_cast<__half2*>(lo + off) = __halves2half2(l0, l1);
}

// ---------------- fused fp32 -> fp16 conversions (one launch) ----------------
__device__ __forceinline__ void cvt4_hl(const float* s, __half* h, __half* l, size_t i) {
    float4 v = *(const float4*)(s + i);
    store_pair_h(h, l, i,     v.x, v.y);
    store_pair_h(h, l, i + 2, v.z, v.w);
}
__device__ __forceinline__ void cvt4_s(const float* s, __half* d, size_t i) {
    float4 v = *(const float4*)(s + i);
    *reinterpret_cast<__half2*>(d + i)     = __halves2half2(__float2half(v.x), __float2half(v.y));
    *reinterpret_cast<__half2*>(d + i + 2) = __halves2half2(__float2half(v.z), __float2half(v.w));
}

__global__ void convert_all_kernel(
    const float* __restrict__ x,  const float* __restrict__ wg,
    const float* __restrict__ wu, const float* __restrict__ wd,
    const float* __restrict__ sg, const float* __restrict__ su,
    const float* __restrict__ sd)
{
    size_t g = (size_t)blockIdx.x * 256 + threadIdx.x;
    const size_t GB = 2097152;   // 8.39M elems / 4
    const size_t GS = 524288;    // 2.10M elems / 4
    if (g < GB) { cvt4_hl(x, g_x_h, g_x_l, g * 4); return; }
    g -= GB;
    if (g < GB) { cvt4_s(wg, g_wg, g * 4); return; }
    g -= GB;
    if (g < GB) { cvt4_s(wu, g_wu, g * 4); return; }
    g -= GB;
    if (g < GB) { cvt4_s(wd, g_wd, g * 4); return; }
    g -= GB;
    if (g < GS) { cvt4_s(sg, g_sg, g * 4); return; }
    g -= GS;
    if (g < GS) { cvt4_s(su, g_su, g * 4); return; }
    g -= GS;
    if (g < GS) { cvt4_s(sd, g_sd, g * 4); return; }
}

// ---------------- router ----------------
__global__ void router_kernel(const float* __restrict__ x, const float* __restrict__ gw)
{
    int warp = threadIdx.x >> 5;
    int lane = threadIdx.x & 31;
    int tok  = blockIdx.x * 8 + warp;
    if (tok >= NTOK) return;
    const float* xr = x + (size_t)tok * HDIM;

    float acc[NEXP];
#pragma unroll
    for (int e = 0; e < NEXP; e++) acc[e] = 0.f;
    for (int h = lane; h < HDIM; h += 32) {
        float xv = xr[h];
#pragma unroll
        for (int e = 0; e < NEXP; e++) acc[e] += xv * gw[e * HDIM + h];
    }
#pragma unroll
    for (int e = 0; e < NEXP; e++) {
#pragma unroll
        for (int off = 16; off > 0; off >>= 1)
            acc[e] += __shfl_xor_sync(0xffffffffu, acc[e], off);
    }
    if (lane == 0) {
        float mx = acc[0];
#pragma unroll
        for (int e = 1; e < NEXP; e++) mx = fmaxf(mx, acc[e]);
        float p[NEXP]; float s = 0.f;
#pragma unroll
        for (int e = 0; e < NEXP; e++) { p[e] = expf(acc[e] - mx); s += p[e]; }
#pragma unroll
        for (int e = 0; e < NEXP; e++) p[e] /= s;
        int i0 = 0;
#pragma unroll
        for (int e = 1; e < NEXP; e++) if (p[e] > p[i0]) i0 = e;
        int i1 = -1;
#pragma unroll
        for (int e = 0; e < NEXP; e++) {
            if (e == i0) continue;
            if (i1 < 0 || p[e] > p[i1]) i1 = e;
        }
        float w0 = p[i0], w1 = p[i1];
        float inv = 1.f / (w0 + w1 + 1e-20f);
        g_topk_idx[tok * 2 + 0] = i0;
        g_topk_idx[tok * 2 + 1] = i1;
        g_topk_w[tok * 2 + 0] = w0 * inv;
        g_topk_w[tok * 2 + 1] = w1 * inv;
    }
}

// ---------------- capacity scan + compaction (reference order) ----------------
__global__ void scan_kernel()
{
    __shared__ int hist[256][NEXP];
    int t = threadIdx.x;
    const int per = (NTOK * TOPK) / 256;
    int local[NEXP];
#pragma unroll
    for (int e = 0; e < NEXP; e++) local[e] = 0;
    int base = t * per;
    for (int i = 0; i < per; i++) local[g_topk_idx[base + i]]++;
#pragma unroll
    for (int e = 0; e < NEXP; e++) hist[t][e] = local[e];
    __syncthreads();
    if (t < NEXP) {
        int run = 0;
        for (int i = 0; i < 256; i++) { int v = hist[i][t]; hist[i][t] = run; run += v; }
        g_counts[t] = run < CAP ? run : CAP;
    }
    __syncthreads();
    int off[NEXP];
#pragma unroll
    for (int e = 0; e < NEXP; e++) off[e] = hist[t][e];
    for (int i = 0; i < per; i++) {
        int slot = base + i;
        int e = g_topk_idx[slot];
        int pos = off[e]++;
        if (pos < CAP) {
            g_etok[e * CAP + pos] = slot >> 1;
            g_ewt[e * CAP + pos]  = g_topk_w[slot];
        }
    }
}

// ============================================================================
// GLU GEMM: O = silu(A@G^T)*(A@U^T) -> fp16 hi/lo
// A fp16 hi/lo, B single fp16: 2 MMA products.
// CTA 128x64, BK=32, 2-stage cp.async ring, 256 threads, 2 CTAs/SM (R9 skeleton).
// ============================================================================
#define GSTG 24576   // per stage: Ah 8K | Al 8K | G 4K | U 4K

__global__ __launch_bounds__(256, 2) void glu_f16_kernel(
    const __half* __restrict__ Ahi, const __half* __restrict__ Alo, int lda,
    const int* __restrict__ rowidx,
    const __half* __restrict__ G_, const __half* __restrict__ U_, size_t bstride,
    __half* __restrict__ Ohi_, __half* __restrict__ Olo_, size_t ostride, int ldo,
    int Kdim, const int* __restrict__ counts)
{
    extern __shared__ __align__(128) char smdyn[];
    const int e = blockIdx.z;
    const int m0 = blockIdx.y * 128, n0 = blockIdx.x * 64;
    if (counts && m0 >= counts[e]) return;

    const char* Gp = (const char*)(G_ + (size_t)e * bstride);
    const char* Up = (const char*)(U_ + (size_t)e * bstride);
    __half* Oh = Ohi_ + (size_t)e * ostride;
    __half* Ol = Olo_ + (size_t)e * ostride;
    const int* ridx = rowidx ? rowidx + e * CAP : nullptr;

    const int tid = threadIdx.x;
    uint32_t smb = (uint32_t)__cvta_generic_to_shared(smdyn);
    const int AH = 0, AL = 8192, Go = 16384, Uo = 20480;

    int ar0 = tid >> 2, ac = tid & 3;          // A rows 0..63, 16B chunk 0..3
    int ar1 = ar0 + 64;
    int tok0 = ridx ? ridx[m0 + ar0] : m0 + ar0;
    int tok1 = ridx ? ridx[m0 + ar1] : m0 + ar1;
    size_t ab0 = ((size_t)tok0 * lda + ac * 8) * 2;
    size_t ab1 = ((size_t)tok1 * lda + ac * 8) * 2;
    size_t bb  = ((size_t)(n0 + ar0) * Kdim + ac * 8) * 2;
    uint32_t dA0 = sw64(ar0 * 64 + ac * 16);
    uint32_t dA1 = sw64(ar1 * 64 + ac * 16);
    const char* pAh = (const char*)Ahi;
    const char* pAl = (const char*)Alo;

    auto load_stage = [&](int kt, int buf) {
        uint32_t s = smb + (uint32_t)buf * GSTG;
        long kb = (long)kt * 64;          // 32 elems * 2B
        cp16(s + AH + dA0, pAh + ab0 + kb);
        cp16(s + AH + dA1, pAh + ab1 + kb);
        cp16(s + AL + dA0, pAl + ab0 + kb);
        cp16(s + AL + dA1, pAl + ab1 + kb);
        cp16(s + Go + dA0, Gp + bb + kb);
        cp16(s + Uo + dA0, Up + bb + kb);
    };

    const int lane = tid & 31, warp = tid >> 5;
    const int wm = warp & 3, wn = warp >> 2;
    const int lr = lane & 15, lc = (lane >> 4) * 16;

    float accG[2][4][4], accU[2][4][4];
#pragma unroll
    for (int mt = 0; mt < 2; mt++)
#pragma unroll
        for (int nf = 0; nf < 4; nf++)
#pragma unroll
            for (int i = 0; i < 4; i++) { accG[mt][nf][i] = 0.f; accU[mt][nf][i] = 0.f; }

    auto comp_stage = [&](int buf) {
        uint32_t s = smb + (uint32_t)buf * GSTG;
#pragma unroll
        for (int kk = 0; kk < 2; kk++) {
            uint32_t ah[2][4], al[2][4];
#pragma unroll
            for (int mt = 0; mt < 2; mt++) {
                uint32_t o = sw64((wm * 32 + mt * 16 + lr) * 64 + kk * 32 + lc);
                ldsm4(ah[mt], s + AH + o);
                ldsm4(al[mt], s + AL + o);
            }
            uint32_t bg[2][4], bu[2][4];
#pragma unroll
            for (int nt = 0; nt < 2; nt++) {
                uint32_t o = sw64((wn * 32 + nt * 16 + lr) * 64 + kk * 32 + lc);
                ldsm4(bg[nt], s + Go + o);
                ldsm4(bu[nt], s + Uo + o);
            }
#pragma unroll
            for (int mt = 0; mt < 2; mt++) {
#pragma unroll
                for (int nf = 0; nf < 4; nf++) {
                    int nt = nf >> 1, f = nf & 1;
                    mma_f16(accG[mt][nf], ah[mt], bg[nt][f], bg[nt][f + 2]);
                    mma_f16(accG[mt][nf], al[mt], bg[nt][f], bg[nt][f + 2]);
                    mma_f16(accU[mt][nf], ah[mt], bu[nt][f], bu[nt][f + 2]);
                    mma_f16(accU[mt][nf], al[mt], bu[nt][f], bu[nt][f + 2]);
                }
            }
        }
    };

    // ---- 2-stage pipeline (R9 double-sync discipline) ----
    const int KT = Kdim >> 5;
    load_stage(0, 0); CP_COMMIT();
    for (int kt = 0; kt < KT; kt++) {
        if (kt + 1 < KT) {
            load_stage(kt + 1, (kt + 1) & 1);
            CP_COMMIT();
            CP_WAIT1();
        } else {
            CP_WAIT0();
        }
        __syncthreads();
        comp_stage(kt & 1);
        __syncthreads();
    }

    // ---- epilogue: silu(g)*u -> fp16 hi/lo ----
    int r0e = m0 + wm * 32 + (lane >> 2);
    int c0e = n0 + wn * 32 + (lane & 3) * 2;
#pragma unroll
    for (int mt = 0; mt < 2; mt++) {
#pragma unroll
        for (int nf = 0; nf < 4; nf++) {
            int r = r0e + mt * 16;
            int c = c0e + nf * 8;
            float v0 = silu_f(accG[mt][nf][0]) * accU[mt][nf][0];
            float v1 = silu_f(accG[mt][nf][1]) * accU[mt][nf][1];
            float v2 = silu_f(accG[mt][nf][2]) * accU[mt][nf][2];
            float v3 = silu_f(accG[mt][nf][3]) * accU[mt][nf][3];
            store_pair_h(Oh, Ol, (size_t)r * ldo + c, v0, v1);
            store_pair_h(Oh, Ol, (size_t)(r + 8) * ldo + c, v2, v3);
        }
    }
}

// ============================================================================
// Down GEMM: out[tok,n] (+)= w * (A@B^T), A fp16 hi/lo, B single fp16, fp32 out
// CTA 128x64, BK=32, 2-stage ring, 256 threads, 2 CTAs/SM.
// ============================================================================
#define DSTG 20480   // per stage: Ah 8K | Al 8K | B 4K

__global__ __launch_bounds__(256, 2) void down_f16_kernel(
    const __half* __restrict__ Ahi_, const __half* __restrict__ Alo_, int lda, size_t astride,
    const __half* __restrict__ B_, size_t bstride,
    const int* __restrict__ rowidx, const float* __restrict__ wts,
    const int* __restrict__ counts, int Mtotal,
    float* __restrict__ out, int ldo, int Kdim, int accumulate)
{
    extern __shared__ __align__(128) char smdyn[];
    const int e = blockIdx.z;
    const int m0 = blockIdx.y * 128, n0 = blockIdx.x * 64;
    if (counts && m0 >= counts[e]) return;

    const char* pAh = (const char*)(Ahi_ + (size_t)e * astride);
    const char* pAl = (const char*)(Alo_ + (size_t)e * astride);
    const char* pB  = (const char*)(B_  + (size_t)e * bstride);

    const int tid = threadIdx.x;
    uint32_t smb = (uint32_t)__cvta_generic_to_shared(smdyn);
    const int AH = 0, AL = 8192, BO = 16384;

    int ar0 = tid >> 2, ac = tid & 3;
    int ar1 = ar0 + 64;
    size_t ab0 = ((size_t)(m0 + ar0) * lda + ac * 8) * 2;
    size_t ab1 = ((size_t)(m0 + ar1) * lda + ac * 8) * 2;
    size_t bb  = ((size_t)(n0 + ar0) * Kdim + ac * 8) * 2;
    uint32_t dA0 = sw64(ar0 * 64 + ac * 16);
    uint32_t dA1 = sw64(ar1 * 64 + ac * 16);

    auto load_stage = [&](int kt, int buf) {
        uint32_t s = smb + (uint32_t)buf * DSTG;
        long kb = (long)kt * 64;
        cp16(s + AH + dA0, pAh + ab0 + kb);
        cp16(s + AH + dA1, pAh + ab1 + kb);
        cp16(s + AL + dA0, pAl + ab0 + kb);
        cp16(s + AL + dA1, pAl + ab1 + kb);
        cp16(s + BO + dA0, pB + bb + kb);
    };

    const int lane = tid & 31, warp = tid >> 5;
    const int wm = warp & 3, wn = warp >> 2;
    const int lr = lane & 15, lc = (lane >> 4) * 16;

    float acc[2][4][4];
#pragma unroll
    for (int mt = 0; mt < 2; mt++)
#pragma unroll
        for (int nf = 0; nf < 4; nf++)
#pragma unroll
            for (int i = 0; i < 4; i++) acc[mt][nf][i] = 0.f;

    auto comp_stage = [&](int buf) {
        uint32_t s = smb + (uint32_t)buf * DSTG;
#pragma unroll
        for (int kk = 0; kk < 2; kk++) {
            uint32_t ah[2][4], al[2][4];
#pragma unroll
            for (int mt = 0; mt < 2; mt++) {
                uint32_t o = sw64((wm * 32 + mt * 16 + lr) * 64 + kk * 32 + lc);
                ldsm4(ah[mt], s + AH + o);
                ldsm4(al[mt], s + AL + o);
            }
            uint32_t bh[2][4];
#pragma unroll
            for (int nt = 0; nt < 2; nt++) {
                uint32_t o = sw64((wn * 32 + nt * 16 + lr) * 64 + kk * 32 + lc);
                ldsm4(bh[nt], s + BO + o);
            }
#pragma unroll
            for (int mt = 0; mt < 2; mt++) {
#pragma unroll
                for (int nf = 0; nf < 4; nf++) {
                    int nt = nf >> 1, f = nf & 1;
                    mma_f16(acc[mt][nf], ah[mt], bh[nt][f], bh[nt][f + 2]);
                    mma_f16(acc[mt][nf], al[mt], bh[nt][f], bh[nt][f + 2]);
                }
            }
        }
    };

    const int KT = Kdim >> 5;
    load_stage(0, 0); CP_COMMIT();
    for (int kt = 0; kt < KT; kt++) {
        if (kt + 1 < KT) {
            load_stage(kt + 1, (kt + 1) & 1);
            CP_COMMIT();
            CP_WAIT1();
        } else {
            CP_WAIT0();
        }
        __syncthreads();
        comp_stage(kt & 1);
        __syncthreads();
    }

    int Mv = counts ? counts[e] : Mtotal;
#pragma unroll
    for (int mt = 0; mt < 2; mt++) {
#pragma unroll
        for (int nf = 0; nf < 4; nf++) {
            int colg = n0 + wn * 32 + nf * 8 + (lane & 3) * 2;
            int r0 = m0 + wm * 32 + mt * 16 + (lane >> 2);
#pragma unroll
            for (int half = 0; half < 2; half++) {
                int r = r0 + half * 8;
                if (r < Mv) {
                    int tok; float w;
                    if (rowidx) { tok = rowidx[e * CAP + r]; w = wts[e * CAP + r]; }
                    else        { tok = r; w = 1.f; }
                    float v0 = acc[mt][nf][half * 2 + 0] * w;
                    float v1 = acc[mt][nf][half * 2 + 1] * w;
                    if (accumulate) {
                        atomicAdd(&out[(size_t)tok * ldo + colg],     v0);
                        atomicAdd(&out[(size_t)tok * ldo + colg + 1], v1);
                    } else {
                        out[(size_t)tok * ldo + colg]     = v0;
                        out[(size_t)tok * ldo + colg + 1] = v1;
                    }
                }
            }
        }
    }
}

// ---------------- launch ----------------
extern "C" void kernel_launch(void* const* d_in, const int* in_sizes, int n_in,
                              void* d_out, int out_size)
{
    const float* x       = (const float*)d_in[0];
    const float* gate_w  = (const float*)d_in[1];
    const float* we_gate = (const float*)d_in[2];
    const float* we_up   = (const float*)d_in[3];
    const float* we_down = (const float*)d_in[4];
    const float* ws_gate = (const float*)d_in[5];
    const float* ws_up   = (const float*)d_in[6];
    const float* ws_down = (const float*)d_in[7];
    float* out = (float*)d_out;

    cudaFuncSetAttribute(glu_f16_kernel,  cudaFuncAttributeMaxDynamicSharedMemorySize, 2 * GSTG);
    cudaFuncSetAttribute(down_f16_kernel, cudaFuncAttributeMaxDynamicSharedMemorySize, 2 * DSTG);

    __half *x_h, *x_l, *wg, *wu, *wd, *sg, *su, *sd;
    __half *ar_h, *ar_l, *as_h, *as_l;
    int *etok, *counts; float *ewt;
    cudaGetSymbolAddress((void**)&x_h, g_x_h); cudaGetSymbolAddress((void**)&x_l, g_x_l);
    cudaGetSymbolAddress((void**)&wg, g_wg);   cudaGetSymbolAddress((void**)&wu, g_wu);
    cudaGetSymbolAddress((void**)&wd, g_wd);
    cudaGetSymbolAddress((void**)&sg, g_sg);   cudaGetSymbolAddress((void**)&su, g_su);
    cudaGetSymbolAddress((void**)&sd, g_sd);
    cudaGetSymbolAddress((void**)&ar_h, g_ar_h); cudaGetSymbolAddress((void**)&ar_l, g_ar_l);
    cudaGetSymbolAddress((void**)&as_h, g_as_h); cudaGetSymbolAddress((void**)&as_l, g_as_l);
    cudaGetSymbolAddress((void**)&etok, g_etok);
    cudaGetSymbolAddress((void**)&ewt,  g_ewt);
    cudaGetSymbolAddress((void**)&counts, g_counts);

    // 1: fused conversion
    convert_all_kernel<<<38912, 256>>>(x, we_gate, we_up, we_down, ws_gate, ws_up, ws_down);
    // 2, 3: router + capacity scan
    router_kernel<<<NTOK / 8, 256>>>(x, gate_w);
    scan_kernel<<<1, 256>>>();

    // 4: shared gate/up + SwiGLU -> g_as
    glu_f16_kernel<<<dim3(SHI / 64, NTOK / 128, 1), 256, 2 * GSTG>>>(
        x_h, x_l, HDIM, nullptr,
        sg, su, 0,
        as_h, as_l, 0, SHI, HDIM, nullptr);

    // 5: shared down-proj (initializes poisoned out)
    down_f16_kernel<<<dim3(HDIM / 64, NTOK / 128, 1), 256, 2 * DSTG>>>(
        as_h, as_l, SHI, 0,
        sd, 0,
        nullptr, nullptr, nullptr, NTOK,
        out, HDIM, SHI, /*accumulate=*/0);

    // 6 (ncu capture slot): routed gate/up + SwiGLU -> g_ar
    glu_f16_kernel<<<dim3(IDIM / 64, CAP / 128, NEXP), 256, 2 * GSTG>>>(
        x_h, x_l, HDIM, etok,
        wg, wu, (size_t)IDIM * HDIM,
        ar_h, ar_l, (size_t)CAP * IDIM, IDIM, HDIM, counts);

    // 7: routed down-proj, weighted atomic scatter
    down_f16_kernel<<<dim3(HDIM / 64, CAP / 128, NEXP), 256, 2 * DSTG>>>(
        ar_h, ar_l, IDIM, (size_t)CAP * IDIM,
        wd, (size_t)HDIM * IDIM,
        etok, ewt, counts, 0,
        out, HDIM, IDIM, /*accumulate=*/1);
}

// round 12
// speedup vs baseline: 5.8785x; 1.6333x over previous
#include <cuda_runtime.h>
#include <cuda_fp16.h>
#include <cstdint>
#include <cstddef>

#define NTOK 8192
#define HDIM 1024
#define NEXP 8
#define TOPK 2
#define IDIM 1024
#define SHI  2048
#define CAP  2560   // ceil(1.25 * 8192 * 2 / 8)

// ---------------- device scratch ----------------
__device__ int   g_topk_idx[NTOK * TOPK];
__device__ float g_topk_w[NTOK * TOPK];
__device__ int   g_etok[NEXP * CAP];
__device__ float g_ewt[NEXP * CAP];
__device__ int   g_counts[NEXP];

// all GEMM operands single fp16
__device__ __align__(128) __half g_x[NTOK * HDIM];
__device__ __align__(128) __half g_wg[NEXP * IDIM * HDIM];
__device__ __align__(128) __half g_wu[NEXP * IDIM * HDIM];
__device__ __align__(128) __half g_wd[NEXP * HDIM * IDIM];
__device__ __align__(128) __half g_sg[SHI * HDIM];
__device__ __align__(128) __half g_su[SHI * HDIM];
__device__ __align__(128) __half g_sd[HDIM * SHI];
__device__ __align__(128) __half g_ar[(size_t)NEXP * CAP * IDIM];
__device__ __align__(128) __half g_as[(size_t)NTOK * SHI];

__device__ __forceinline__ float silu_f(float x) { return x / (1.f + __expf(-x)); }
__device__ __forceinline__ uint32_t sw64(uint32_t b) { return b ^ ((b >> 3) & 0x30); }

__device__ __forceinline__ void cp16(uint32_t dst, const void* src) {
    asm volatile("cp.async.cg.shared.global [%0], [%1], 16;" :: "r"(dst), "l"(src));
}
#define CP_COMMIT() asm volatile("cp.async.commit_group;")
#define CP_WAIT1()  asm volatile("cp.async.wait_group 1;")
#define CP_WAIT0()  asm volatile("cp.async.wait_group 0;")

__device__ __forceinline__ void ldsm4(uint32_t* r, uint32_t addr) {
    asm volatile("ldmatrix.sync.aligned.m8n8.x4.shared.b16 {%0,%1,%2,%3}, [%4];"
                 : "=r"(r[0]), "=r"(r[1]), "=r"(r[2]), "=r"(r[3]) : "r"(addr));
}

__device__ __forceinline__ void mma_f16(float (&c)[4], const uint32_t (&a)[4],
                                        uint32_t b0, uint32_t b1)
{
    asm volatile(
        "mma.sync.aligned.m16n8k16.row.col.f32.f16.f16.f32 "
        "{%0,%1,%2,%3}, {%4,%5,%6,%7}, {%8,%9}, {%0,%1,%2,%3};\n"
        : "+f"(c[0]), "+f"(c[1]), "+f"(c[2]), "+f"(c[3])
        : "r"(a[0]), "r"(a[1]), "r"(a[2]), "r"(a[3]), "r"(b0), "r"(b1));
}

// ---------------- fused fp32 -> fp16 conversion (one launch) ----------------
__device__ __forceinline__ void cvt4_s(const float* s, __half* d, size_t i) {
    float4 v = *(const float4*)(s + i);
    *reinterpret_cast<__half2*>(d + i)     = __halves2half2(__float2half(v.x), __float2half(v.y));
    *reinterpret_cast<__half2*>(d + i + 2) = __halves2half2(__float2half(v.z), __float2half(v.w));
}

__global__ void convert_all_kernel(
    const float* __restrict__ x,  const float* __restrict__ wg,
    const float* __restrict__ wu, const float* __restrict__ wd,
    const float* __restrict__ sg, const float* __restrict__ su,
    const float* __restrict__ sd)
{
    size_t g = (size_t)blockIdx.x * 256 + threadIdx.x;
    const size_t GB = 2097152;   // 8.39M elems / 4
    const size_t GS = 524288;    // 2.10M elems / 4
    if (g < GB) { cvt4_s(x,  g_x,  g * 4); return; }
    g -= GB;
    if (g < GB) { cvt4_s(wg, g_wg, g * 4); return; }
    g -= GB;
    if (g < GB) { cvt4_s(wu, g_wu, g * 4); return; }
    g -= GB;
    if (g < GB) { cvt4_s(wd, g_wd, g * 4); return; }
    g -= GB;
    if (g < GS) { cvt4_s(sg, g_sg, g * 4); return; }
    g -= GS;
    if (g < GS) { cvt4_s(su, g_su, g * 4); return; }
    g -= GS;
    if (g < GS) { cvt4_s(sd, g_sd, g * 4); return; }
}

// ---------------- router ----------------
__global__ void router_kernel(const float* __restrict__ x, const float* __restrict__ gw)
{
    int warp = threadIdx.x >> 5;
    int lane = threadIdx.x & 31;
    int tok  = blockIdx.x * 8 + warp;
    if (tok >= NTOK) return;
    const float* xr = x + (size_t)tok * HDIM;

    float acc[NEXP];
#pragma unroll
    for (int e = 0; e < NEXP; e++) acc[e] = 0.f;
    for (int h = lane; h < HDIM; h += 32) {
        float xv = xr[h];
#pragma unroll
        for (int e = 0; e < NEXP; e++) acc[e] += xv * gw[e * HDIM + h];
    }
#pragma unroll
    for (int e = 0; e < NEXP; e++) {
#pragma unroll
        for (int off = 16; off > 0; off >>= 1)
            acc[e] += __shfl_xor_sync(0xffffffffu, acc[e], off);
    }
    if (lane == 0) {
        float mx = acc[0];
#pragma unroll
        for (int e = 1; e < NEXP; e++) mx = fmaxf(mx, acc[e]);
        float p[NEXP]; float s = 0.f;
#pragma unroll
        for (int e = 0; e < NEXP; e++) { p[e] = expf(acc[e] - mx); s += p[e]; }
#pragma unroll
        for (int e = 0; e < NEXP; e++) p[e] /= s;
        int i0 = 0;
#pragma unroll
        for (int e = 1; e < NEXP; e++) if (p[e] > p[i0]) i0 = e;
        int i1 = -1;
#pragma unroll
        for (int e = 0; e < NEXP; e++) {
            if (e == i0) continue;
            if (i1 < 0 || p[e] > p[i1]) i1 = e;
        }
        float w0 = p[i0], w1 = p[i1];
        float inv = 1.f / (w0 + w1 + 1e-20f);
        g_topk_idx[tok * 2 + 0] = i0;
        g_topk_idx[tok * 2 + 1] = i1;
        g_topk_w[tok * 2 + 0] = w0 * inv;
        g_topk_w[tok * 2 + 1] = w1 * inv;
    }
}

// ---------------- capacity scan + compaction (reference order) ----------------
__global__ void scan_kernel()
{
    __shared__ int hist[256][NEXP];
    int t = threadIdx.x;
    const int per = (NTOK * TOPK) / 256;
    int local[NEXP];
#pragma unroll
    for (int e = 0; e < NEXP; e++) local[e] = 0;
    int base = t * per;
    for (int i = 0; i < per; i++) local[g_topk_idx[base + i]]++;
#pragma unroll
    for (int e = 0; e < NEXP; e++) hist[t][e] = local[e];
    __syncthreads();
    if (t < NEXP) {
        int run = 0;
        for (int i = 0; i < 256; i++) { int v = hist[i][t]; hist[i][t] = run; run += v; }
        g_counts[t] = run < CAP ? run : CAP;
    }
    __syncthreads();
    int off[NEXP];
#pragma unroll
    for (int e = 0; e < NEXP; e++) off[e] = hist[t][e];
    for (int i = 0; i < per; i++) {
        int slot = base + i;
        int e = g_topk_idx[slot];
        int pos = off[e]++;
        if (pos < CAP) {
            g_etok[e * CAP + pos] = slot >> 1;
            g_ewt[e * CAP + pos]  = g_topk_w[slot];
        }
    }
}

// ============================================================================
// GLU GEMM: O = silu(A@G^T)*(A@U^T) -> fp16 (single product, fp32 acc)
// CTA 128x64, BK=32, 2-stage cp.async ring, 256 threads, 2 CTAs/SM (R10 skeleton).
// ============================================================================
#define GSTG 16384   // per stage: A 8K | G 4K | U 4K

__global__ __launch_bounds__(256, 2) void glu_f16_kernel(
    const __half* __restrict__ A_, int lda,
    const int* __restrict__ rowidx,
    const __half* __restrict__ G_, const __half* __restrict__ U_, size_t bstride,
    __half* __restrict__ O_, size_t ostride, int ldo,
    int Kdim, const int* __restrict__ counts)
{
    extern __shared__ __align__(128) char smdyn[];
    const int e = blockIdx.z;
    const int m0 = blockIdx.y * 128, n0 = blockIdx.x * 64;
    if (counts && m0 >= counts[e]) return;

    const char* Gp = (const char*)(G_ + (size_t)e * bstride);
    const char* Up = (const char*)(U_ + (size_t)e * bstride);
    __half* O = O_ + (size_t)e * ostride;
    const int* ridx = rowidx ? rowidx + e * CAP : nullptr;

    const int tid = threadIdx.x;
    uint32_t smb = (uint32_t)__cvta_generic_to_shared(smdyn);
    const int AO = 0, Go = 8192, Uo = 12288;

    int ar0 = tid >> 2, ac = tid & 3;          // A rows 0..63, 16B chunk 0..3
    int ar1 = ar0 + 64;
    int tok0 = ridx ? ridx[m0 + ar0] : m0 + ar0;
    int tok1 = ridx ? ridx[m0 + ar1] : m0 + ar1;
    size_t ab0 = ((size_t)tok0 * lda + ac * 8) * 2;
    size_t ab1 = ((size_t)tok1 * lda + ac * 8) * 2;
    size_t bb  = ((size_t)(n0 + ar0) * Kdim + ac * 8) * 2;
    uint32_t dA0 = sw64(ar0 * 64 + ac * 16);
    uint32_t dA1 = sw64(ar1 * 64 + ac * 16);
    const char* pA = (const char*)A_;

    auto load_stage = [&](int kt, int buf) {
        uint32_t s = smb + (uint32_t)buf * GSTG;
        long kb = (long)kt * 64;          // 32 elems * 2B
        cp16(s + AO + dA0, pA + ab0 + kb);
        cp16(s + AO + dA1, pA + ab1 + kb);
        cp16(s + Go + dA0, Gp + bb + kb);
        cp16(s + Uo + dA0, Up + bb + kb);
    };

    const int lane = tid & 31, warp = tid >> 5;
    const int wm = warp & 3, wn = warp >> 2;
    const int lr = lane & 15, lc = (lane >> 4) * 16;

    float accG[2][4][4], accU[2][4][4];
#pragma unroll
    for (int mt = 0; mt < 2; mt++)
#pragma unroll
        for (int nf = 0; nf < 4; nf++)
#pragma unroll
            for (int i = 0; i < 4; i++) { accG[mt][nf][i] = 0.f; accU[mt][nf][i] = 0.f; }

    auto comp_stage = [&](int buf) {
        uint32_t s = smb + (uint32_t)buf * GSTG;
#pragma unroll
        for (int kk = 0; kk < 2; kk++) {
            uint32_t ah[2][4];
#pragma unroll
            for (int mt = 0; mt < 2; mt++) {
                uint32_t o = sw64((wm * 32 + mt * 16 + lr) * 64 + kk * 32 + lc);
                ldsm4(ah[mt], s + AO + o);
            }
            uint32_t bg[2][4], bu[2][4];
#pragma unroll
            for (int nt = 0; nt < 2; nt++) {
                uint32_t o = sw64((wn * 32 + nt * 16 + lr) * 64 + kk * 32 + lc);
                ldsm4(bg[nt], s + Go + o);
                ldsm4(bu[nt], s + Uo + o);
            }
#pragma unroll
            for (int mt = 0; mt < 2; mt++) {
#pragma unroll
                for (int nf = 0; nf < 4; nf++) {
                    int nt = nf >> 1, f = nf & 1;
                    mma_f16(accG[mt][nf], ah[mt], bg[nt][f], bg[nt][f + 2]);
                    mma_f16(accU[mt][nf], ah[mt], bu[nt][f], bu[nt][f + 2]);
                }
            }
        }
    };

    // ---- 2-stage pipeline (double-sync discipline) ----
    const int KT = Kdim >> 5;
    load_stage(0, 0); CP_COMMIT();
    for (int kt = 0; kt < KT; kt++) {
        if (kt + 1 < KT) {
            load_stage(kt + 1, (kt + 1) & 1);
            CP_COMMIT();
            CP_WAIT1();
        } else {
            CP_WAIT0();
        }
        __syncthreads();
        comp_stage(kt & 1);
        __syncthreads();
    }

    // ---- epilogue: silu(g)*u -> fp16 ----
    int r0e = m0 + wm * 32 + (lane >> 2);
    int c0e = n0 + wn * 32 + (lane & 3) * 2;
#pragma unroll
    for (int mt = 0; mt < 2; mt++) {
#pragma unroll
        for (int nf = 0; nf < 4; nf++) {
            int r = r0e + mt * 16;
            int c = c0e + nf * 8;
            float v0 = silu_f(accG[mt][nf][0]) * accU[mt][nf][0];
            float v1 = silu_f(accG[mt][nf][1]) * accU[mt][nf][1];
            float v2 = silu_f(accG[mt][nf][2]) * accU[mt][nf][2];
            float v3 = silu_f(accG[mt][nf][3]) * accU[mt][nf][3];
            *reinterpret_cast<__half2*>(O + (size_t)r * ldo + c) =
                __halves2half2(__float2half(v0), __float2half(v1));
            *reinterpret_cast<__half2*>(O + (size_t)(r + 8) * ldo + c) =
                __halves2half2(__float2half(v2), __float2half(v3));
        }
    }
}

// ============================================================================
// Down GEMM: out[tok,n] (+)= w * (A@B^T), fp16 x fp16, fp32 acc/out
// CTA 128x64, BK=32, 2-stage ring, 256 threads, 2 CTAs/SM.
// ============================================================================
#define DSTG 12288   // per stage: A 8K | B 4K

__global__ __launch_bounds__(256, 2) void down_f16_kernel(
    const __half* __restrict__ A_, int lda, size_t astride,
    const __half* __restrict__ B_, size_t bstride,
    const int* __restrict__ rowidx, const float* __restrict__ wts,
    const int* __restrict__ counts, int Mtotal,
    float* __restrict__ out, int ldo, int Kdim, int accumulate)
{
    extern __shared__ __align__(128) char smdyn[];
    const int e = blockIdx.z;
    const int m0 = blockIdx.y * 128, n0 = blockIdx.x * 64;
    if (counts && m0 >= counts[e]) return;

    const char* pA = (const char*)(A_ + (size_t)e * astride);
    const char* pB = (const char*)(B_ + (size_t)e * bstride);

    const int tid = threadIdx.x;
    uint32_t smb = (uint32_t)__cvta_generic_to_shared(smdyn);
    const int AO = 0, BO = 8192;

    int ar0 = tid >> 2, ac = tid & 3;
    int ar1 = ar0 + 64;
    size_t ab0 = ((size_t)(m0 + ar0) * lda + ac * 8) * 2;
    size_t ab1 = ((size_t)(m0 + ar1) * lda + ac * 8) * 2;
    size_t bb  = ((size_t)(n0 + ar0) * Kdim + ac * 8) * 2;
    uint32_t dA0 = sw64(ar0 * 64 + ac * 16);
    uint32_t dA1 = sw64(ar1 * 64 + ac * 16);

    auto load_stage = [&](int kt, int buf) {
        uint32_t s = smb + (uint32_t)buf * DSTG;
        long kb = (long)kt * 64;
        cp16(s + AO + dA0, pA + ab0 + kb);
        cp16(s + AO + dA1, pA + ab1 + kb);
        cp16(s + BO + dA0, pB + bb + kb);
    };

    const int lane = tid & 31, warp = tid >> 5;
    const int wm = warp & 3, wn = warp >> 2;
    const int lr = lane & 15, lc = (lane >> 4) * 16;

    float acc[2][4][4];
#pragma unroll
    for (int mt = 0; mt < 2; mt++)
#pragma unroll
        for (int nf = 0; nf < 4; nf++)
#pragma unroll
            for (int i = 0; i < 4; i++) acc[mt][nf][i] = 0.f;

    auto comp_stage = [&](int buf) {
        uint32_t s = smb + (uint32_t)buf * DSTG;
#pragma unroll
        for (int kk = 0; kk < 2; kk++) {
            uint32_t ah[2][4];
#pragma unroll
            for (int mt = 0; mt < 2; mt++) {
                uint32_t o = sw64((wm * 32 + mt * 16 + lr) * 64 + kk * 32 + lc);
                ldsm4(ah[mt], s + AO + o);
            }
            uint32_t bh[2][4];
#pragma unroll
            for (int nt = 0; nt < 2; nt++) {
                uint32_t o = sw64((wn * 32 + nt * 16 + lr) * 64 + kk * 32 + lc);
                ldsm4(bh[nt], s + BO + o);
            }
#pragma unroll
            for (int mt = 0; mt < 2; mt++) {
#pragma unroll
                for (int nf = 0; nf < 4; nf++) {
                    int nt = nf >> 1, f = nf & 1;
                    mma_f16(acc[mt][nf], ah[mt], bh[nt][f], bh[nt][f + 2]);
                }
            }
        }
    };

    const int KT = Kdim >> 5;
    load_stage(0, 0); CP_COMMIT();
    for (int kt = 0; kt < KT; kt++) {
        if (kt + 1 < KT) {
            load_stage(kt + 1, (kt + 1) & 1);
            CP_COMMIT();
            CP_WAIT1();
        } else {
            CP_WAIT0();
        }
        __syncthreads();
        comp_stage(kt & 1);
        __syncthreads();
    }

    int Mv = counts ? counts[e] : Mtotal;
#pragma unroll
    for (int mt = 0; mt < 2; mt++) {
#pragma unroll
        for (int nf = 0; nf < 4; nf++) {
            int colg = n0 + wn * 32 + nf * 8 + (lane & 3) * 2;
            int r0 = m0 + wm * 32 + mt * 16 + (lane >> 2);
#pragma unroll
            for (int half = 0; half < 2; half++) {
                int r = r0 + half * 8;
                if (r < Mv) {
                    int tok; float w;
                    if (rowidx) { tok = rowidx[e * CAP + r]; w = wts[e * CAP + r]; }
                    else        { tok = r; w = 1.f; }
                    float v0 = acc[mt][nf][half * 2 + 0] * w;
                    float v1 = acc[mt][nf][half * 2 + 1] * w;
                    if (accumulate) {
                        atomicAdd(&out[(size_t)tok * ldo + colg],     v0);
                        atomicAdd(&out[(size_t)tok * ldo + colg + 1], v1);
                    } else {
                        out[(size_t)tok * ldo + colg]     = v0;
                        out[(size_t)tok * ldo + colg + 1] = v1;
                    }
                }
            }
        }
    }
}

// ---------------- launch ----------------
extern "C" void kernel_launch(void* const* d_in, const int* in_sizes, int n_in,
                              void* d_out, int out_size)
{
    const float* x       = (const float*)d_in[0];
    const float* gate_w  = (const float*)d_in[1];
    const float* we_gate = (const float*)d_in[2];
    const float* we_up   = (const float*)d_in[3];
    const float* we_down = (const float*)d_in[4];
    const float* ws_gate = (const float*)d_in[5];
    const float* ws_up   = (const float*)d_in[6];
    const float* ws_down = (const float*)d_in[7];
    float* out = (float*)d_out;

    cudaFuncSetAttribute(glu_f16_kernel,  cudaFuncAttributeMaxDynamicSharedMemorySize, 2 * GSTG);
    cudaFuncSetAttribute(down_f16_kernel, cudaFuncAttributeMaxDynamicSharedMemorySize, 2 * DSTG);

    __half *xh, *wg, *wu, *wd, *sg, *su, *sd, *ar, *as;
    int *etok, *counts; float *ewt;
    cudaGetSymbolAddress((void**)&xh, g_x);
    cudaGetSymbolAddress((void**)&wg, g_wg);   cudaGetSymbolAddress((void**)&wu, g_wu);
    cudaGetSymbolAddress((void**)&wd, g_wd);
    cudaGetSymbolAddress((void**)&sg, g_sg);   cudaGetSymbolAddress((void**)&su, g_su);
    cudaGetSymbolAddress((void**)&sd, g_sd);
    cudaGetSymbolAddress((void**)&ar, g_ar);   cudaGetSymbolAddress((void**)&as, g_as);
    cudaGetSymbolAddress((void**)&etok, g_etok);
    cudaGetSymbolAddress((void**)&ewt,  g_ewt);
    cudaGetSymbolAddress((void**)&counts, g_counts);

    // 1: fused conversion
    convert_all_kernel<<<38912, 256>>>(x, we_gate, we_up, we_down, ws_gate, ws_up, ws_down);
    // 2, 3: router + capacity scan
    router_kernel<<<NTOK / 8, 256>>>(x, gate_w);
    scan_kernel<<<1, 256>>>();

    // 4: shared gate/up + SwiGLU -> g_as
    glu_f16_kernel<<<dim3(SHI / 64, NTOK / 128, 1), 256, 2 * GSTG>>>(
        xh, HDIM, nullptr,
        sg, su, 0,
        as, 0, SHI, HDIM, nullptr);

    // 5: shared down-proj (initializes poisoned out)
    down_f16_kernel<<<dim3(HDIM / 64, NTOK / 128, 1), 256, 2 * DSTG>>>(
        as, SHI, 0,
        sd, 0,
        nullptr, nullptr, nullptr, NTOK,
        out, HDIM, SHI, /*accumulate=*/0);

    // 6 (ncu capture slot): routed gate/up + SwiGLU -> g_ar
    glu_f16_kernel<<<dim3(IDIM / 64, CAP / 128, NEXP), 256, 2 * GSTG>>>(
        xh, HDIM, etok,
        wg, wu, (size_t)IDIM * HDIM,
        ar, (size_t)CAP * IDIM, IDIM, HDIM, counts);

    // 7: routed down-proj, weighted atomic scatter
    down_f16_kernel<<<dim3(HDIM / 64, CAP / 128, NEXP), 256, 2 * DSTG>>>(
        ar, IDIM, (size_t)CAP * IDIM,
        wd, (size_t)HDIM * IDIM,
        etok, ewt, counts, 0,
        out, HDIM, IDIM, /*accumulate=*/1);
}

// round 14
// speedup vs baseline: 6.7046x; 1.1405x over previous
#include <cuda_runtime.h>
#include <cuda_fp16.h>
#include <cstdint>
#include <cstddef>

#define NTOK 8192
#define HDIM 1024
#define NEXP 8
#define TOPK 2
#define IDIM 1024
#define SHI  2048
#define CAP  2560   // ceil(1.25 * 8192 * 2 / 8)

// ---------------- device scratch ----------------
__device__ int   g_topk_idx[NTOK * TOPK];
__device__ float g_topk_w[NTOK * TOPK];
__device__ int   g_etok[NEXP * CAP];
__device__ float g_ewt[NEXP * CAP];
__device__ int   g_counts[NEXP];

// all GEMM operands single fp16
__device__ __align__(128) __half g_x[NTOK * HDIM];
__device__ __align__(128) __half g_wg[NEXP * IDIM * HDIM];
__device__ __align__(128) __half g_wu[NEXP * IDIM * HDIM];
__device__ __align__(128) __half g_wd[NEXP * HDIM * IDIM];
__device__ __align__(128) __half g_sg[SHI * HDIM];
__device__ __align__(128) __half g_su[SHI * HDIM];
__device__ __align__(128) __half g_sd[HDIM * SHI];
__device__ __align__(128) __half g_ar[(size_t)NEXP * CAP * IDIM];
__device__ __align__(128) __half g_as[(size_t)NTOK * SHI];

__device__ __forceinline__ float silu_f(float x) { return x / (1.f + __expf(-x)); }
__device__ __forceinline__ uint32_t sw128(uint32_t b) { return b ^ ((b >> 3) & 0x70); }

__device__ __forceinline__ void cp16(uint32_t dst, const void* src) {
    asm volatile("cp.async.cg.shared.global [%0], [%1], 16;" :: "r"(dst), "l"(src));
}
#define CP_COMMIT() asm volatile("cp.async.commit_group;")
#define CP_WAIT1()  asm volatile("cp.async.wait_group 1;")
#define CP_WAIT0()  asm volatile("cp.async.wait_group 0;")

__device__ __forceinline__ void ldsm4(uint32_t* r, uint32_t addr) {
    asm volatile("ldmatrix.sync.aligned.m8n8.x4.shared.b16 {%0,%1,%2,%3}, [%4];"
                 : "=r"(r[0]), "=r"(r[1]), "=r"(r[2]), "=r"(r[3]) : "r"(addr));
}

__device__ __forceinline__ void mma_f16(float (&c)[4], const uint32_t (&a)[4],
                                        uint32_t b0, uint32_t b1)
{
    asm volatile(
        "mma.sync.aligned.m16n8k16.row.col.f32.f16.f16.f32 "
        "{%0,%1,%2,%3}, {%4,%5,%6,%7}, {%8,%9}, {%0,%1,%2,%3};\n"
        : "+f"(c[0]), "+f"(c[1]), "+f"(c[2]), "+f"(c[3])
        : "r"(a[0]), "r"(a[1]), "r"(a[2]), "r"(a[3]), "r"(b0), "r"(b1));
}

// ---------------- fused fp32 -> fp16 conversion (one launch) ----------------
__device__ __forceinline__ void cvt4_s(const float* s, __half* d, size_t i) {
    float4 v = *(const float4*)(s + i);
    *reinterpret_cast<__half2*>(d + i)     = __halves2half2(__float2half(v.x), __float2half(v.y));
    *reinterpret_cast<__half2*>(d + i + 2) = __halves2half2(__float2half(v.z), __float2half(v.w));
}

__global__ void convert_all_kernel(
    const float* __restrict__ x,  const float* __restrict__ wg,
    const float* __restrict__ wu, const float* __restrict__ wd,
    const float* __restrict__ sg, const float* __restrict__ su,
    const float* __restrict__ sd)
{
    size_t g = (size_t)blockIdx.x * 256 + threadIdx.x;
    const size_t GB = 2097152;   // 8.39M elems / 4
    const size_t GS = 524288;    // 2.10M elems / 4
    if (g < GB) { cvt4_s(x,  g_x,  g * 4); return; }
    g -= GB;
    if (g < GB) { cvt4_s(wg, g_wg, g * 4); return; }
    g -= GB;
    if (g < GB) { cvt4_s(wu, g_wu, g * 4); return; }
    g -= GB;
    if (g < GB) { cvt4_s(wd, g_wd, g * 4); return; }
    g -= GB;
    if (g < GS) { cvt4_s(sg, g_sg, g * 4); return; }
    g -= GS;
    if (g < GS) { cvt4_s(su, g_su, g * 4); return; }
    g -= GS;
    if (g < GS) { cvt4_s(sd, g_sd, g * 4); return; }
}

// ---------------- router ----------------
__global__ void router_kernel(const float* __restrict__ x, const float* __restrict__ gw)
{
    int warp = threadIdx.x >> 5;
    int lane = threadIdx.x & 31;
    int tok  = blockIdx.x * 8 + warp;
    if (tok >= NTOK) return;
    const float* xr = x + (size_t)tok * HDIM;

    float acc[NEXP];
#pragma unroll
    for (int e = 0; e < NEXP; e++) acc[e] = 0.f;
    for (int h = lane; h < HDIM; h += 32) {
        float xv = xr[h];
#pragma unroll
        for (int e = 0; e < NEXP; e++) acc[e] += xv * gw[e * HDIM + h];
    }
#pragma unroll
    for (int e = 0; e < NEXP; e++) {
#pragma unroll
        for (int off = 16; off > 0; off >>= 1)
            acc[e] += __shfl_xor_sync(0xffffffffu, acc[e], off);
    }
    if (lane == 0) {
        float mx = acc[0];
#pragma unroll
        for (int e = 1; e < NEXP; e++) mx = fmaxf(mx, acc[e]);
        float p[NEXP]; float s = 0.f;
#pragma unroll
        for (int e = 0; e < NEXP; e++) { p[e] = expf(acc[e] - mx); s += p[e]; }
#pragma unroll
        for (int e = 0; e < NEXP; e++) p[e] /= s;
        int i0 = 0;
#pragma unroll
        for (int e = 1; e < NEXP; e++) if (p[e] > p[i0]) i0 = e;
        int i1 = -1;
#pragma unroll
        for (int e = 0; e < NEXP; e++) {
            if (e == i0) continue;
            if (i1 < 0 || p[e] > p[i1]) i1 = e;
        }
        float w0 = p[i0], w1 = p[i1];
        float inv = 1.f / (w0 + w1 + 1e-20f);
        g_topk_idx[tok * 2 + 0] = i0;
        g_topk_idx[tok * 2 + 1] = i1;
        g_topk_w[tok * 2 + 0] = w0 * inv;
        g_topk_w[tok * 2 + 1] = w1 * inv;
    }
}

// ---------------- capacity scan + compaction (reference order) ----------------
__global__ void scan_kernel()
{
    __shared__ int hist[256][NEXP];
    int t = threadIdx.x;
    const int per = (NTOK * TOPK) / 256;
    int local[NEXP];
#pragma unroll
    for (int e = 0; e < NEXP; e++) local[e] = 0;
    int base = t * per;
    for (int i = 0; i < per; i++) local[g_topk_idx[base + i]]++;
#pragma unroll
    for (int e = 0; e < NEXP; e++) hist[t][e] = local[e];
    __syncthreads();
    if (t < NEXP) {
        int run = 0;
        for (int i = 0; i < 256; i++) { int v = hist[i][t]; hist[i][t] = run; run += v; }
        g_counts[t] = run < CAP ? run : CAP;
    }
    __syncthreads();
    int off[NEXP];
#pragma unroll
    for (int e = 0; e < NEXP; e++) off[e] = hist[t][e];
    for (int i = 0; i < per; i++) {
        int slot = base + i;
        int e = g_topk_idx[slot];
        int pos = off[e]++;
        if (pos < CAP) {
            g_etok[e * CAP + pos] = slot >> 1;
            g_ewt[e * CAP + pos]  = g_topk_w[slot];
        }
    }
}

// ============================================================================
// GLU GEMM: O = silu(A@G^T)*(A@U^T) -> fp16 (single product, fp32 acc)
// CTA 128x64, BK=64, 2-stage cp.async ring, 256 threads, 2 CTAs/SM.
// ============================================================================
#define GSTG 32768   // per stage: A 16K | G 8K | U 8K

__global__ __launch_bounds__(256, 2) void glu_f16_kernel(
    const __half* __restrict__ A_, int lda,
    const int* __restrict__ rowidx,
    const __half* __restrict__ G_, const __half* __restrict__ U_, size_t bstride,
    __half* __restrict__ O_, size_t ostride, int ldo,
    int Kdim, const int* __restrict__ counts)
{
    extern __shared__ __align__(128) char smdyn[];
    const int e = blockIdx.z;
    const int m0 = blockIdx.y * 128, n0 = blockIdx.x * 64;
    if (counts && m0 >= counts[e]) return;

    const char* Gp = (const char*)(G_ + (size_t)e * bstride);
    const char* Up = (const char*)(U_ + (size_t)e * bstride);
    __half* O = O_ + (size_t)e * ostride;
    const int* ridx = rowidx ? rowidx + e * CAP : nullptr;

    const int tid = threadIdx.x;
    uint32_t smb = (uint32_t)__cvta_generic_to_shared(smdyn);
    const int AO = 0, Go = 16384, Uo = 24576;

    // loader: rows = ar + 32*i (A: i=0..3, B: i=0..1), 16B chunk ac within 128B row
    int ar = tid >> 3;              // 0..31
    int ac = (tid & 7) * 16;        // 0..112
    size_t abase[4];
#pragma unroll
    for (int i = 0; i < 4; i++) {
        int row = m0 + ar + 32 * i;
        int tok = ridx ? ridx[row] : row;
        abase[i] = (size_t)tok * lda * 2 + ac;
    }
    size_t bb = (size_t)(n0 + ar) * Kdim * 2 + ac;
    const size_t bstep = (size_t)32 * Kdim * 2;
    uint32_t dA = sw128(ar * 128 + ac);
    const char* pA = (const char*)A_;

    auto load_stage = [&](int kt, int buf) {
        uint32_t s = smb + (uint32_t)buf * GSTG;
        long kb = (long)kt * 128;      // 64 halves * 2B
#pragma unroll
        for (int i = 0; i < 4; i++)
            cp16(s + AO + dA + i * 4096, pA + abase[i] + kb);
        cp16(s + Go + dA,        Gp + bb + kb);
        cp16(s + Go + dA + 4096, Gp + bb + bstep + kb);
        cp16(s + Uo + dA,        Up + bb + kb);
        cp16(s + Uo + dA + 4096, Up + bb + bstep + kb);
    };

    const int lane = tid & 31, warp = tid >> 5;
    const int wm = warp & 3, wn = warp >> 2;
    const int lr = lane & 15, lc = (lane >> 4) * 16;

    float accG[2][4][4], accU[2][4][4];
#pragma unroll
    for (int mt = 0; mt < 2; mt++)
#pragma unroll
        for (int nf = 0; nf < 4; nf++)
#pragma unroll
            for (int i = 0; i < 4; i++) { accG[mt][nf][i] = 0.f; accU[mt][nf][i] = 0.f; }

    auto comp_stage = [&](int buf) {
        uint32_t s = smb + (uint32_t)buf * GSTG;
#pragma unroll
        for (int kk = 0; kk < 4; kk++) {
            uint32_t ah[2][4];
#pragma unroll
            for (int mt = 0; mt < 2; mt++) {
                uint32_t o = sw128((wm * 32 + mt * 16 + lr) * 128 + kk * 32 + lc);
                ldsm4(ah[mt], s + AO + o);
            }
            uint32_t bg[2][4], bu[2][4];
#pragma unroll
            for (int nt = 0; nt < 2; nt++) {
                uint32_t o = sw128((wn * 32 + nt * 16 + lr) * 128 + kk * 32 + lc);
                ldsm4(bg[nt], s + Go + o);
                ldsm4(bu[nt], s + Uo + o);
            }
#pragma unroll
            for (int mt = 0; mt < 2; mt++) {
#pragma unroll
                for (int nf = 0; nf < 4; nf++) {
                    int nt = nf >> 1, f = nf & 1;
                    mma_f16(accG[mt][nf], ah[mt], bg[nt][f], bg[nt][f + 2]);
                    mma_f16(accU[mt][nf], ah[mt], bu[nt][f], bu[nt][f + 2]);
                }
            }
        }
    };

    // ---- 2-stage pipeline (double-sync discipline) ----
    const int KT = Kdim >> 6;
    load_stage(0, 0); CP_COMMIT();
    for (int kt = 0; kt < KT; kt++) {
        if (kt + 1 < KT) {
            load_stage(kt + 1, (kt + 1) & 1);
            CP_COMMIT();
            CP_WAIT1();
        } else {
            CP_WAIT0();
        }
        __syncthreads();
        comp_stage(kt & 1);
        __syncthreads();
    }

    // ---- epilogue: silu(g)*u -> fp16 ----
    int r0e = m0 + wm * 32 + (lane >> 2);
    int c0e = n0 + wn * 32 + (lane & 3) * 2;
#pragma unroll
    for (int mt = 0; mt < 2; mt++) {
#pragma unroll
        for (int nf = 0; nf < 4; nf++) {
            int r = r0e + mt * 16;
            int c = c0e + nf * 8;
            float v0 = silu_f(accG[mt][nf][0]) * accU[mt][nf][0];
            float v1 = silu_f(accG[mt][nf][1]) * accU[mt][nf][1];
            float v2 = silu_f(accG[mt][nf][2]) * accU[mt][nf][2];
            float v3 = silu_f(accG[mt][nf][3]) * accU[mt][nf][3];
            *reinterpret_cast<__half2*>(O + (size_t)r * ldo + c) =
                __halves2half2(__float2half(v0), __float2half(v1));
            *reinterpret_cast<__half2*>(O + (size_t)(r + 8) * ldo + c) =
                __halves2half2(__float2half(v2), __float2half(v3));
        }
    }
}

// ============================================================================
// Down GEMM: out[tok,n] (+)= w * (A@B^T), fp16 x fp16, fp32 acc/out
// CTA 128x64, BK=64, 2-stage ring, 256 threads, 2 CTAs/SM.
// ============================================================================
#define DSTG 24576   // per stage: A 16K | B 8K

__global__ __launch_bounds__(256, 2) void down_f16_kernel(
    const __half* __restrict__ A_, int lda, size_t astride,
    const __half* __restrict__ B_, size_t bstride,
    const int* __restrict__ rowidx, const float* __restrict__ wts,
    const int* __restrict__ counts, int Mtotal,
    float* __restrict__ out, int ldo, int Kdim, int accumulate)
{
    extern __shared__ __align__(128) char smdyn[];
    const int e = blockIdx.z;
    const int m0 = blockIdx.y * 128, n0 = blockIdx.x * 64;
    if (counts && m0 >= counts[e]) return;

    const char* pA = (const char*)(A_ + (size_t)e * astride);
    const char* pB = (const char*)(B_ + (size_t)e * bstride);

    const int tid = threadIdx.x;
    uint32_t smb = (uint32_t)__cvta_generic_to_shared(smdyn);
    const int AO = 0, BO = 16384;

    int ar = tid >> 3;              // 0..31
    int ac = (tid & 7) * 16;
    size_t ab = (size_t)(m0 + ar) * lda * 2 + ac;
    const size_t astep = (size_t)32 * lda * 2;
    size_t bb = (size_t)(n0 + ar) * Kdim * 2 + ac;
    const size_t bstep = (size_t)32 * Kdim * 2;
    uint32_t dA = sw128(ar * 128 + ac);

    auto load_stage = [&](int kt, int buf) {
        uint32_t s = smb + (uint32_t)buf * DSTG;
        long kb = (long)kt * 128;
#pragma unroll
        for (int i = 0; i < 4; i++)
            cp16(s + AO + dA + i * 4096, pA + ab + (size_t)i * astep + kb);
        cp16(s + BO + dA,        pB + bb + kb);
        cp16(s + BO + dA + 4096, pB + bb + bstep + kb);
    };

    const int lane = tid & 31, warp = tid >> 5;
    const int wm = warp & 3, wn = warp >> 2;
    const int lr = lane & 15, lc = (lane >> 4) * 16;

    float acc[2][4][4];
#pragma unroll
    for (int mt = 0; mt < 2; mt++)
#pragma unroll
        for (int nf = 0; nf < 4; nf++)
#pragma unroll
            for (int i = 0; i < 4; i++) acc[mt][nf][i] = 0.f;

    auto comp_stage = [&](int buf) {
        uint32_t s = smb + (uint32_t)buf * DSTG;
#pragma unroll
        for (int kk = 0; kk < 4; kk++) {
            uint32_t ah[2][4];
#pragma unroll
            for (int mt = 0; mt < 2; mt++) {
                uint32_t o = sw128((wm * 32 + mt * 16 + lr) * 128 + kk * 32 + lc);
                ldsm4(ah[mt], s + AO + o);
            }
            uint32_t bh[2][4];
#pragma unroll
            for (int nt = 0; nt < 2; nt++) {
                uint32_t o = sw128((wn * 32 + nt * 16 + lr) * 128 + kk * 32 + lc);
                ldsm4(bh[nt], s + BO + o);
            }
#pragma unroll
            for (int mt = 0; mt < 2; mt++) {
#pragma unroll
                for (int nf = 0; nf < 4; nf++) {
                    int nt = nf >> 1, f = nf & 1;
                    mma_f16(acc[mt][nf], ah[mt], bh[nt][f], bh[nt][f + 2]);
                }
            }
        }
    };

    const int KT = Kdim >> 6;
    load_stage(0, 0); CP_COMMIT();
    for (int kt = 0; kt < KT; kt++) {
        if (kt + 1 < KT) {
            load_stage(kt + 1, (kt + 1) & 1);
            CP_COMMIT();
            CP_WAIT1();
        } else {
            CP_WAIT0();
        }
        __syncthreads();
        comp_stage(kt & 1);
        __syncthreads();
    }

    int Mv = counts ? counts[e] : Mtotal;
#pragma unroll
    for (int mt = 0; mt < 2; mt++) {
#pragma unroll
        for (int nf = 0; nf < 4; nf++) {
            int colg = n0 + wn * 32 + nf * 8 + (lane & 3) * 2;
            int r0 = m0 + wm * 32 + mt * 16 + (lane >> 2);
#pragma unroll
            for (int half = 0; half < 2; half++) {
                int r = r0 + half * 8;
                if (r < Mv) {
                    int tok; float w;
                    if (rowidx) { tok = rowidx[e * CAP + r]; w = wts[e * CAP + r]; }
                    else        { tok = r; w = 1.f; }
                    float v0 = acc[mt][nf][half * 2 + 0] * w;
                    float v1 = acc[mt][nf][half * 2 + 1] * w;
                    if (accumulate) {
                        atomicAdd(&out[(size_t)tok * ldo + colg],     v0);
                        atomicAdd(&out[(size_t)tok * ldo + colg + 1], v1);
                    } else {
                        out[(size_t)tok * ldo + colg]     = v0;
                        out[(size_t)tok * ldo + colg + 1] = v1;
                    }
                }
            }
        }
    }
}

// ---------------- launch ----------------
extern "C" void kernel_launch(void* const* d_in, const int* in_sizes, int n_in,
                              void* d_out, int out_size)
{
    const float* x       = (const float*)d_in[0];
    const float* gate_w  = (const float*)d_in[1];
    const float* we_gate = (const float*)d_in[2];
    const float* we_up   = (const float*)d_in[3];
    const float* we_down = (const float*)d_in[4];
    const float* ws_gate = (const float*)d_in[5];
    const float* ws_up   = (const float*)d_in[6];
    const float* ws_down = (const float*)d_in[7];
    float* out = (float*)d_out;

    cudaFuncSetAttribute(glu_f16_kernel,  cudaFuncAttributeMaxDynamicSharedMemorySize, 2 * GSTG);
    cudaFuncSetAttribute(down_f16_kernel, cudaFuncAttributeMaxDynamicSharedMemorySize, 2 * DSTG);

    __half *xh, *wg, *wu, *wd, *sg, *su, *sd, *ar, *as;
    int *etok, *counts; float *ewt;
    cudaGetSymbolAddress((void**)&xh, g_x);
    cudaGetSymbolAddress((void**)&wg, g_wg);   cudaGetSymbolAddress((void**)&wu, g_wu);
    cudaGetSymbolAddress((void**)&wd, g_wd);
    cudaGetSymbolAddress((void**)&sg, g_sg);   cudaGetSymbolAddress((void**)&su, g_su);
    cudaGetSymbolAddress((void**)&sd, g_sd);
    cudaGetSymbolAddress((void**)&ar, g_ar);   cudaGetSymbolAddress((void**)&as, g_as);
    cudaGetSymbolAddress((void**)&etok, g_etok);
    cudaGetSymbolAddress((void**)&ewt,  g_ewt);
    cudaGetSymbolAddress((void**)&counts, g_counts);

    // 1: fused conversion
    convert_all_kernel<<<38912, 256>>>(x, we_gate, we_up, we_down, ws_gate, ws_up, ws_down);
    // 2, 3: router + capacity scan
    router_kernel<<<NTOK / 8, 256>>>(x, gate_w);
    scan_kernel<<<1, 256>>>();

    // 4: shared gate/up + SwiGLU -> g_as
    glu_f16_kernel<<<dim3(SHI / 64, NTOK / 128, 1), 256, 2 * GSTG>>>(
        xh, HDIM, nullptr,
        sg, su, 0,
        as, 0, SHI, HDIM, nullptr);

    // 5: shared down-proj (initializes poisoned out)
    down_f16_kernel<<<dim3(HDIM / 64, NTOK / 128, 1), 256, 2 * DSTG>>>(
        as, SHI, 0,
        sd, 0,
        nullptr, nullptr, nullptr, NTOK,
        out, HDIM, SHI, /*accumulate=*/0);

    // 6 (ncu capture slot): routed gate/up + SwiGLU -> g_ar
    glu_f16_kernel<<<dim3(IDIM / 64, CAP / 128, NEXP), 256, 2 * GSTG>>>(
        xh, HDIM, etok,
        wg, wu, (size_t)IDIM * HDIM,
        ar, (size_t)CAP * IDIM, IDIM, HDIM, counts);

    // 7: routed down-proj, weighted atomic scatter
    down_f16_kernel<<<dim3(HDIM / 64, CAP / 128, NEXP), 256, 2 * DSTG>>>(
        ar, IDIM, (size_t)CAP * IDIM,
        wd, (size_t)HDIM * IDIM,
        etok, ewt, counts, 0,
        out, HDIM, IDIM, /*accumulate=*/1);
}

// round 15
// speedup vs baseline: 6.9021x; 1.0294x over previous
#include <cuda_runtime.h>
#include <cuda_fp16.h>
#include <cstdint>
#include <cstddef>

#define NTOK 8192
#define HDIM 1024
#define NEXP 8
#define TOPK 2
#define IDIM 1024
#define SHI  2048
#define CAP  2560   // ceil(1.25 * 8192 * 2 / 8)

// ---------------- device scratch ----------------
__device__ int   g_topk_idx[NTOK * TOPK];
__device__ float g_topk_w[NTOK * TOPK];
__device__ int   g_etok[NEXP * CAP];
__device__ float g_ewt[NEXP * CAP];
__device__ int   g_counts[NEXP];

// all GEMM operands single fp16
__device__ __align__(128) __half g_x[NTOK * HDIM];
__device__ __align__(128) __half g_wg[NEXP * IDIM * HDIM];
__device__ __align__(128) __half g_wu[NEXP * IDIM * HDIM];
__device__ __align__(128) __half g_wd[NEXP * HDIM * IDIM];
__device__ __align__(128) __half g_sg[SHI * HDIM];
__device__ __align__(128) __half g_su[SHI * HDIM];
__device__ __align__(128) __half g_sd[HDIM * SHI];
__device__ __align__(128) __half g_ar[(size_t)NEXP * CAP * IDIM];
__device__ __align__(128) __half g_as[(size_t)NTOK * SHI];

__device__ __forceinline__ float silu_f(float x) { return x / (1.f + __expf(-x)); }
__device__ __forceinline__ uint32_t sw128(uint32_t b) { return b ^ ((b >> 3) & 0x70); }

__device__ __forceinline__ void cp16(uint32_t dst, const void* src) {
    asm volatile("cp.async.cg.shared.global [%0], [%1], 16;" :: "r"(dst), "l"(src));
}
#define CP_COMMIT() asm volatile("cp.async.commit_group;")
#define CP_WAIT1()  asm volatile("cp.async.wait_group 1;")
#define CP_WAIT0()  asm volatile("cp.async.wait_group 0;")

__device__ __forceinline__ void ldsm4(uint32_t* r, uint32_t addr) {
    asm volatile("ldmatrix.sync.aligned.m8n8.x4.shared.b16 {%0,%1,%2,%3}, [%4];"
                 : "=r"(r[0]), "=r"(r[1]), "=r"(r[2]), "=r"(r[3]) : "r"(addr));
}

__device__ __forceinline__ void mma_f16(float (&c)[4], const uint32_t (&a)[4],
                                        uint32_t b0, uint32_t b1)
{
    asm volatile(
        "mma.sync.aligned.m16n8k16.row.col.f32.f16.f16.f32 "
        "{%0,%1,%2,%3}, {%4,%5,%6,%7}, {%8,%9}, {%0,%1,%2,%3};\n"
        : "+f"(c[0]), "+f"(c[1]), "+f"(c[2]), "+f"(c[3])
        : "r"(a[0]), "r"(a[1]), "r"(a[2]), "r"(a[3]), "r"(b0), "r"(b1));
}

// ---------------- fused fp32 -> fp16 conversion (one launch) ----------------
__device__ __forceinline__ void cvt4_s(const float* s, __half* d, size_t i) {
    float4 v = *(const float4*)(s + i);
    *reinterpret_cast<__half2*>(d + i)     = __halves2half2(__float2half(v.x), __float2half(v.y));
    *reinterpret_cast<__half2*>(d + i + 2) = __halves2half2(__float2half(v.z), __float2half(v.w));
}

__global__ void convert_all_kernel(
    const float* __restrict__ x,  const float* __restrict__ wg,
    const float* __restrict__ wu, const float* __restrict__ wd,
    const float* __restrict__ sg, const float* __restrict__ su,
    const float* __restrict__ sd)
{
    size_t g = (size_t)blockIdx.x * 256 + threadIdx.x;
    const size_t GB = 2097152;   // 8.39M elems / 4
    const size_t GS = 524288;    // 2.10M elems / 4
    if (g < GB) { cvt4_s(x,  g_x,  g * 4); return; }
    g -= GB;
    if (g < GB) { cvt4_s(wg, g_wg, g * 4); return; }
    g -= GB;
    if (g < GB) { cvt4_s(wu, g_wu, g * 4); return; }
    g -= GB;
    if (g < GB) { cvt4_s(wd, g_wd, g * 4); return; }
    g -= GB;
    if (g < GS) { cvt4_s(sg, g_sg, g * 4); return; }
    g -= GS;
    if (g < GS) { cvt4_s(su, g_su, g * 4); return; }
    g -= GS;
    if (g < GS) { cvt4_s(sd, g_sd, g * 4); return; }
}

// ---------------- router ----------------
__global__ void router_kernel(const float* __restrict__ x, const float* __restrict__ gw)
{
    int warp = threadIdx.x >> 5;
    int lane = threadIdx.x & 31;
    int tok  = blockIdx.x * 8 + warp;
    if (tok >= NTOK) return;
    const float* xr = x + (size_t)tok * HDIM;

    float acc[NEXP];
#pragma unroll
    for (int e = 0; e < NEXP; e++) acc[e] = 0.f;
    for (int h = lane; h < HDIM; h += 32) {
        float xv = xr[h];
#pragma unroll
        for (int e = 0; e < NEXP; e++) acc[e] += xv * gw[e * HDIM + h];
    }
#pragma unroll
    for (int e = 0; e < NEXP; e++) {
#pragma unroll
        for (int off = 16; off > 0; off >>= 1)
            acc[e] += __shfl_xor_sync(0xffffffffu, acc[e], off);
    }
    if (lane == 0) {
        float mx = acc[0];
#pragma unroll
        for (int e = 1; e < NEXP; e++) mx = fmaxf(mx, acc[e]);
        float p[NEXP]; float s = 0.f;
#pragma unroll
        for (int e = 0; e < NEXP; e++) { p[e] = expf(acc[e] - mx); s += p[e]; }
#pragma unroll
        for (int e = 0; e < NEXP; e++) p[e] /= s;
        int i0 = 0;
#pragma unroll
        for (int e = 1; e < NEXP; e++) if (p[e] > p[i0]) i0 = e;
        int i1 = -1;
#pragma unroll
        for (int e = 0; e < NEXP; e++) {
            if (e == i0) continue;
            if (i1 < 0 || p[e] > p[i1]) i1 = e;
        }
        float w0 = p[i0], w1 = p[i1];
        float inv = 1.f / (w0 + w1 + 1e-20f);
        g_topk_idx[tok * 2 + 0] = i0;
        g_topk_idx[tok * 2 + 1] = i1;
        g_topk_w[tok * 2 + 0] = w0 * inv;
        g_topk_w[tok * 2 + 1] = w1 * inv;
    }
}

// ---------------- capacity scan + compaction (reference order) ----------------
__global__ void scan_kernel()
{
    __shared__ int hist[256][NEXP];
    int t = threadIdx.x;
    const int per = (NTOK * TOPK) / 256;
    int local[NEXP];
#pragma unroll
    for (int e = 0; e < NEXP; e++) local[e] = 0;
    int base = t * per;
    for (int i = 0; i < per; i++) local[g_topk_idx[base + i]]++;
#pragma unroll
    for (int e = 0; e < NEXP; e++) hist[t][e] = local[e];
    __syncthreads();
    if (t < NEXP) {
        int run = 0;
        for (int i = 0; i < 256; i++) { int v = hist[i][t]; hist[i][t] = run; run += v; }
        g_counts[t] = run < CAP ? run : CAP;
    }
    __syncthreads();
    int off[NEXP];
#pragma unroll
    for (int e = 0; e < NEXP; e++) off[e] = hist[t][e];
    for (int i = 0; i < per; i++) {
        int slot = base + i;
        int e = g_topk_idx[slot];
        int pos = off[e]++;
        if (pos < CAP) {
            g_etok[e * CAP + pos] = slot >> 1;
            g_ewt[e * CAP + pos]  = g_topk_w[slot];
        }
    }
}

// ============================================================================
// GLU GEMM: O = silu(A@G^T)*(A@U^T) -> fp16 (single product, fp32 acc)
// CTA 128x64, BK=64, 2-stage cp.async ring, 256 threads, 2 CTAs/SM.  (R14 winner)
// ============================================================================
#define GSTG 32768   // per stage: A 16K | G 8K | U 8K

__global__ __launch_bounds__(256, 2) void glu_f16_kernel(
    const __half* __restrict__ A_, int lda,
    const int* __restrict__ rowidx,
    const __half* __restrict__ G_, const __half* __restrict__ U_, size_t bstride,
    __half* __restrict__ O_, size_t ostride, int ldo,
    int Kdim, const int* __restrict__ counts)
{
    extern __shared__ __align__(128) char smdyn[];
    const int e = blockIdx.z;
    const int m0 = blockIdx.y * 128, n0 = blockIdx.x * 64;
    if (counts && m0 >= counts[e]) return;

    const char* Gp = (const char*)(G_ + (size_t)e * bstride);
    const char* Up = (const char*)(U_ + (size_t)e * bstride);
    __half* O = O_ + (size_t)e * ostride;
    const int* ridx = rowidx ? rowidx + e * CAP : nullptr;

    const int tid = threadIdx.x;
    uint32_t smb = (uint32_t)__cvta_generic_to_shared(smdyn);
    const int AO = 0, Go = 16384, Uo = 24576;

    int ar = tid >> 3;              // 0..31
    int ac = (tid & 7) * 16;        // 0..112
    size_t abase[4];
#pragma unroll
    for (int i = 0; i < 4; i++) {
        int row = m0 + ar + 32 * i;
        int tok = ridx ? ridx[row] : row;
        abase[i] = (size_t)tok * lda * 2 + ac;
    }
    size_t bb = (size_t)(n0 + ar) * Kdim * 2 + ac;
    const size_t bstep = (size_t)32 * Kdim * 2;
    uint32_t dA = sw128(ar * 128 + ac);
    const char* pA = (const char*)A_;

    auto load_stage = [&](int kt, int buf) {
        uint32_t s = smb + (uint32_t)buf * GSTG;
        long kb = (long)kt * 128;      // 64 halves * 2B
#pragma unroll
        for (int i = 0; i < 4; i++)
            cp16(s + AO + dA + i * 4096, pA + abase[i] + kb);
        cp16(s + Go + dA,        Gp + bb + kb);
        cp16(s + Go + dA + 4096, Gp + bb + bstep + kb);
        cp16(s + Uo + dA,        Up + bb + kb);
        cp16(s + Uo + dA + 4096, Up + bb + bstep + kb);
    };

    const int lane = tid & 31, warp = tid >> 5;
    const int wm = warp & 3, wn = warp >> 2;
    const int lr = lane & 15, lc = (lane >> 4) * 16;

    float accG[2][4][4], accU[2][4][4];
#pragma unroll
    for (int mt = 0; mt < 2; mt++)
#pragma unroll
        for (int nf = 0; nf < 4; nf++)
#pragma unroll
            for (int i = 0; i < 4; i++) { accG[mt][nf][i] = 0.f; accU[mt][nf][i] = 0.f; }

    auto comp_stage = [&](int buf) {
        uint32_t s = smb + (uint32_t)buf * GSTG;
#pragma unroll
        for (int kk = 0; kk < 4; kk++) {
            uint32_t ah[2][4];
#pragma unroll
            for (int mt = 0; mt < 2; mt++) {
                uint32_t o = sw128((wm * 32 + mt * 16 + lr) * 128 + kk * 32 + lc);
                ldsm4(ah[mt], s + AO + o);
            }
            uint32_t bg[2][4], bu[2][4];
#pragma unroll
            for (int nt = 0; nt < 2; nt++) {
                uint32_t o = sw128((wn * 32 + nt * 16 + lr) * 128 + kk * 32 + lc);
                ldsm4(bg[nt], s + Go + o);
                ldsm4(bu[nt], s + Uo + o);
            }
#pragma unroll
            for (int mt = 0; mt < 2; mt++) {
#pragma unroll
                for (int nf = 0; nf < 4; nf++) {
                    int nt = nf >> 1, f = nf & 1;
                    mma_f16(accG[mt][nf], ah[mt], bg[nt][f], bg[nt][f + 2]);
                    mma_f16(accU[mt][nf], ah[mt], bu[nt][f], bu[nt][f + 2]);
                }
            }
        }
    };

    const int KT = Kdim >> 6;
    load_stage(0, 0); CP_COMMIT();
    for (int kt = 0; kt < KT; kt++) {
        if (kt + 1 < KT) {
            load_stage(kt + 1, (kt + 1) & 1);
            CP_COMMIT();
            CP_WAIT1();
        } else {
            CP_WAIT0();
        }
        __syncthreads();
        comp_stage(kt & 1);
        __syncthreads();
    }

    int r0e = m0 + wm * 32 + (lane >> 2);
    int c0e = n0 + wn * 32 + (lane & 3) * 2;
#pragma unroll
    for (int mt = 0; mt < 2; mt++) {
#pragma unroll
        for (int nf = 0; nf < 4; nf++) {
            int r = r0e + mt * 16;
            int c = c0e + nf * 8;
            float v0 = silu_f(accG[mt][nf][0]) * accU[mt][nf][0];
            float v1 = silu_f(accG[mt][nf][1]) * accU[mt][nf][1];
            float v2 = silu_f(accG[mt][nf][2]) * accU[mt][nf][2];
            float v3 = silu_f(accG[mt][nf][3]) * accU[mt][nf][3];
            *reinterpret_cast<__half2*>(O + (size_t)r * ldo + c) =
                __halves2half2(__float2half(v0), __float2half(v1));
            *reinterpret_cast<__half2*>(O + (size_t)(r + 8) * ldo + c) =
                __halves2half2(__float2half(v2), __float2half(v3));
        }
    }
}

// ============================================================================
// Down GEMM: out[tok,n] (+)= w * (A@B^T), fp16 x fp16, fp32 acc/out
// CTA 128x128, BK=64, warp grid 4x2 (warp tile 32x64), 2-stage ring,
// 256 threads, 2 CTAs/SM.
// ============================================================================
#define DSTG 32768   // per stage: A 16K | B 16K

__global__ __launch_bounds__(256, 2) void down_f16_kernel(
    const __half* __restrict__ A_, int lda, size_t astride,
    const __half* __restrict__ B_, size_t bstride,
    const int* __restrict__ rowidx, const float* __restrict__ wts,
    const int* __restrict__ counts, int Mtotal,
    float* __restrict__ out, int ldo, int Kdim, int accumulate)
{
    extern __shared__ __align__(128) char smdyn[];
    const int e = blockIdx.z;
    const int m0 = blockIdx.y * 128, n0 = blockIdx.x * 128;
    if (counts && m0 >= counts[e]) return;

    const char* pA = (const char*)(A_ + (size_t)e * astride);
    const char* pB = (const char*)(B_ + (size_t)e * bstride);

    const int tid = threadIdx.x;
    uint32_t smb = (uint32_t)__cvta_generic_to_shared(smdyn);
    const int AO = 0, BO = 16384;

    int ar = tid >> 3;              // 0..31
    int ac = (tid & 7) * 16;
    size_t ab = (size_t)(m0 + ar) * lda * 2 + ac;
    const size_t astep = (size_t)32 * lda * 2;
    size_t bb = (size_t)(n0 + ar) * Kdim * 2 + ac;
    const size_t bstep = (size_t)32 * Kdim * 2;
    uint32_t dA = sw128(ar * 128 + ac);

    auto load_stage = [&](int kt, int buf) {
        uint32_t s = smb + (uint32_t)buf * DSTG;
        long kb = (long)kt * 128;
#pragma unroll
        for (int i = 0; i < 4; i++) {
            cp16(s + AO + dA + i * 4096, pA + ab + (size_t)i * astep + kb);
            cp16(s + BO + dA + i * 4096, pB + bb + (size_t)i * bstep + kb);
        }
    };

    const int lane = tid & 31, warp = tid >> 5;
    const int wm = warp & 3, wn = warp >> 2;   // wm 0..3 (M), wn 0..1 (N)
    const int lr = lane & 15, lc = (lane >> 4) * 16;

    float acc[2][8][4];
#pragma unroll
    for (int mt = 0; mt < 2; mt++)
#pragma unroll
        for (int nf = 0; nf < 8; nf++)
#pragma unroll
            for (int i = 0; i < 4; i++) acc[mt][nf][i] = 0.f;

    auto comp_stage = [&](int buf) {
        uint32_t s = smb + (uint32_t)buf * DSTG;
#pragma unroll
        for (int kk = 0; kk < 4; kk++) {
            uint32_t ah[2][4];
#pragma unroll
            for (int mt = 0; mt < 2; mt++) {
                uint32_t o = sw128((wm * 32 + mt * 16 + lr) * 128 + kk * 32 + lc);
                ldsm4(ah[mt], s + AO + o);
            }
            uint32_t bh[4][4];
#pragma unroll
            for (int nt = 0; nt < 4; nt++) {
                uint32_t o = sw128((wn * 64 + nt * 16 + lr) * 128 + kk * 32 + lc);
                ldsm4(bh[nt], s + BO + o);
            }
#pragma unroll
            for (int mt = 0; mt < 2; mt++) {
#pragma unroll
                for (int nf = 0; nf < 8; nf++) {
                    int nt = nf >> 1, f = nf & 1;
                    mma_f16(acc[mt][nf], ah[mt], bh[nt][f], bh[nt][f + 2]);
                }
            }
        }
    };

    const int KT = Kdim >> 6;
    load_stage(0, 0); CP_COMMIT();
    for (int kt = 0; kt < KT; kt++) {
        if (kt + 1 < KT) {
            load_stage(kt + 1, (kt + 1) & 1);
            CP_COMMIT();
            CP_WAIT1();
        } else {
            CP_WAIT0();
        }
        __syncthreads();
        comp_stage(kt & 1);
        __syncthreads();
    }

    int Mv = counts ? counts[e] : Mtotal;
#pragma unroll
    for (int mt = 0; mt < 2; mt++) {
#pragma unroll
        for (int half = 0; half < 2; half++) {
            int r = m0 + wm * 32 + mt * 16 + (lane >> 2) + half * 8;
            if (r >= Mv) continue;
            int tok = r; float w = 1.f;
            if (rowidx) { tok = rowidx[e * CAP + r]; w = wts[e * CAP + r]; }
            float* orow = out + (size_t)tok * ldo;
#pragma unroll
            for (int nf = 0; nf < 8; nf++) {
                int c = n0 + wn * 64 + nf * 8 + (lane & 3) * 2;
                float v0 = acc[mt][nf][half * 2 + 0] * w;
                float v1 = acc[mt][nf][half * 2 + 1] * w;
                if (accumulate) {
                    atomicAdd(&orow[c],     v0);
                    atomicAdd(&orow[c + 1], v1);
                } else {
                    orow[c]     = v0;
                    orow[c + 1] = v1;
                }
            }
        }
    }
}

// ---------------- launch ----------------
extern "C" void kernel_launch(void* const* d_in, const int* in_sizes, int n_in,
                              void* d_out, int out_size)
{
    const float* x       = (const float*)d_in[0];
    const float* gate_w  = (const float*)d_in[1];
    const float* we_gate = (const float*)d_in[2];
    const float* we_up   = (const float*)d_in[3];
    const float* we_down = (const float*)d_in[4];
    const float* ws_gate = (const float*)d_in[5];
    const float* ws_up   = (const float*)d_in[6];
    const float* ws_down = (const float*)d_in[7];
    float* out = (float*)d_out;

    cudaFuncSetAttribute(glu_f16_kernel,  cudaFuncAttributeMaxDynamicSharedMemorySize, 2 * GSTG);
    cudaFuncSetAttribute(down_f16_kernel, cudaFuncAttributeMaxDynamicSharedMemorySize, 2 * DSTG);

    __half *xh, *wg, *wu, *wd, *sg, *su, *sd, *ar, *as;
    int *etok, *counts; float *ewt;
    cudaGetSymbolAddress((void**)&xh, g_x);
    cudaGetSymbolAddress((void**)&wg, g_wg);   cudaGetSymbolAddress((void**)&wu, g_wu);
    cudaGetSymbolAddress((void**)&wd, g_wd);
    cudaGetSymbolAddress((void**)&sg, g_sg);   cudaGetSymbolAddress((void**)&su, g_su);
    cudaGetSymbolAddress((void**)&sd, g_sd);
    cudaGetSymbolAddress((void**)&ar, g_ar);   cudaGetSymbolAddress((void**)&as, g_as);
    cudaGetSymbolAddress((void**)&etok, g_etok);
    cudaGetSymbolAddress((void**)&ewt,  g_ewt);
    cudaGetSymbolAddress((void**)&counts, g_counts);

    // 1: fused conversion
    convert_all_kernel<<<38912, 256>>>(x, we_gate, we_up, we_down, ws_gate, ws_up, ws_down);
    // 2, 3: router + capacity scan
    router_kernel<<<NTOK / 8, 256>>>(x, gate_w);
    scan_kernel<<<1, 256>>>();

    // 4: shared gate/up + SwiGLU -> g_as
    glu_f16_kernel<<<dim3(SHI / 64, NTOK / 128, 1), 256, 2 * GSTG>>>(
        xh, HDIM, nullptr,
        sg, su, 0,
        as, 0, SHI, HDIM, nullptr);

    // 5: shared down-proj (initializes poisoned out)
    down_f16_kernel<<<dim3(HDIM / 128, NTOK / 128, 1), 256, 2 * DSTG>>>(
        as, SHI, 0,
        sd, 0,
        nullptr, nullptr, nullptr, NTOK,
        out, HDIM, SHI, /*accumulate=*/0);

    // 6 (ncu capture slot): routed gate/up + SwiGLU -> g_ar
    glu_f16_kernel<<<dim3(IDIM / 64, CAP / 128, NEXP), 256, 2 * GSTG>>>(
        xh, HDIM, etok,
        wg, wu, (size_t)IDIM * HDIM,
        ar, (size_t)CAP * IDIM, IDIM, HDIM, counts);

    // 7: routed down-proj, weighted atomic scatter
    down_f16_kernel<<<dim3(HDIM / 128, CAP / 128, NEXP), 256, 2 * DSTG>>>(
        ar, IDIM, (size_t)CAP * IDIM,
        wd, (size_t)HDIM * IDIM,
        etok, ewt, counts, 0,
        out, HDIM, IDIM, /*accumulate=*/1);
}